// round 13
// baseline (speedup 1.0000x reference)
#include <cuda_runtime.h>
#include <cuda_fp16.h>
#include <cuda_bf16.h>
#include <cstdint>

// ---------------------------------------------------------------------------
// Problem constants
// ---------------------------------------------------------------------------
#define BB    16
#define TT    2048
#define DIM   1024
#define NST   64
#define MTOT  (BB * TT)          // 32768 rows

// HMMA GEMM tiling: CTA tile 256x128, warp tile 64x64 (8 warps, 4x2)
#define BM    256
#define BN    128
#define BK    16
#define LDSK  24                 // padded halves per smem row (48B)
#define AT_B  (256 * LDSK * 2)   // 12288 B  (Ah or Al tile)
#define BT_B  (128 * LDSK * 2)   // 6144 B   (Bh or Bl tile)
#define STG_B (2 * AT_B + 2 * BT_B)   // 36864 B per stage
#define SMEM_H (3 * STG_B)            // 110592 B (3 stages)

// ---------------------------------------------------------------------------
// Scratch (__device__ globals — no allocation allowed)
// ---------------------------------------------------------------------------
__device__ __align__(16) __half g_xhh[(size_t)MTOT * DIM];  // x hi
__device__ __align__(16) __half g_xhl[(size_t)MTOT * DIM];  // x lo
__device__ __align__(16) __half g_xph[(size_t)MTOT * DIM];  // xp hi
__device__ __align__(16) __half g_xpl[(size_t)MTOT * DIM];  // xp lo
__device__ __align__(16) __half g_wih[(size_t)DIM * DIM];   // W_in hi
__device__ __align__(16) __half g_wil[(size_t)DIM * DIM];   // W_in lo
__device__ __align__(16) __half g_wch[(size_t)256 * DIM];   // wcat hi
__device__ __align__(16) __half g_wcl[(size_t)256 * DIM];   // wcat lo
__device__ float g_kvqa[(size_t)MTOT * 256];   // 32 MB : [m][k|v|q|ax]
__device__ float g_cell[(size_t)MTOT * NST];   //  8 MB : gated cell output

// ---------------------------------------------------------------------------
// Helpers
// ---------------------------------------------------------------------------
__device__ __forceinline__ float fast_sigmoid(float x) {
    return __fdividef(1.0f, 1.0f + __expf(-x));
}

__device__ __forceinline__ uint32_t smem_u32(const void* p) {
    uint32_t a;
    asm("{ .reg .u64 t; cvta.to.shared.u64 t, %1; cvt.u32.u64 %0, t; }"
        : "=r"(a) : "l"(p));
    return a;
}

__device__ __forceinline__ void cp16(uint32_t dst, const void* src) {
    asm volatile("cp.async.cg.shared.global [%0], [%1], 16;"
                 :: "r"(dst), "l"(src));
}

__device__ __forceinline__ uint32_t lds32(uint32_t a) {
    uint32_t v;
    asm("ld.shared.b32 %0, [%1];" : "=r"(v) : "r"(a));
    return v;
}

__device__ __forceinline__ void mma16816(float* c, const uint32_t* a,
                                         const uint32_t* b) {
    asm volatile(
        "mma.sync.aligned.m16n8k16.row.col.f32.f16.f16.f32 "
        "{%0,%1,%2,%3}, {%4,%5,%6,%7}, {%8,%9}, {%0,%1,%2,%3};"
        : "+f"(c[0]), "+f"(c[1]), "+f"(c[2]), "+f"(c[3])
        : "r"(a[0]), "r"(a[1]), "r"(a[2]), "r"(a[3]), "r"(b[0]), "r"(b[1]));
}

__device__ __forceinline__ void ffma2(unsigned long long &acc,
                                      unsigned long long a,
                                      unsigned long long b) {
    asm("fma.rn.f32x2 %0, %1, %2, %0;" : "+l"(acc) : "l"(a), "l"(b));
}
__device__ __forceinline__ unsigned long long splat2(float v) {
    unsigned long long r;
    asm("mov.b64 %0, {%1, %1};" : "=l"(r) : "r"(__float_as_uint(v)));
    return r;
}

__device__ __forceinline__ void split_hl(float v, __half& h, __half& l) {
    h = __float2half_rn(v);
    l = __float2half_rn(v - __half2float(h));
}

// ---------------------------------------------------------------------------
// Conversion kernels: fp32 -> fp16 hi/lo, row-major, 8 elems per thread
// ---------------------------------------------------------------------------
__global__ void conv_hl_kernel(const float* __restrict__ src,
                               __half* __restrict__ hi,
                               __half* __restrict__ lo, int n8) {
    int t = blockIdx.x * blockDim.x + threadIdx.x;
    if (t >= n8) return;
    const float4* s = (const float4*)(src + (size_t)t * 8);
    float4 a = s[0], b = s[1];
    float v[8] = {a.x, a.y, a.z, a.w, b.x, b.y, b.z, b.w};
    __half hv[8], lv[8];
#pragma unroll
    for (int i = 0; i < 8; i++) split_hl(v[i], hv[i], lv[i]);
    *(uint4*)(hi + (size_t)t * 8) = *(uint4*)hv;
    *(uint4*)(lo + (size_t)t * 8) = *(uint4*)lv;
}

// wcat = concat(W_k,W_v,W_q,W_alpha)[256][1024] -> hi/lo
__global__ void conv_wcat_kernel(const float* __restrict__ Wk,
                                 const float* __restrict__ Wv,
                                 const float* __restrict__ Wq,
                                 const float* __restrict__ Wa,
                                 __half* __restrict__ hi,
                                 __half* __restrict__ lo) {
    int t = blockIdx.x * blockDim.x + threadIdx.x;   // 32768 threads
    if (t >= 256 * DIM / 8) return;
    int e0 = t * 8;
    int n = e0 >> 10;
    int j = e0 & 1023;
    const float* src = (n < 64) ? Wk : (n < 128) ? Wv : (n < 192) ? Wq : Wa;
    const float4* s = (const float4*)(src + (size_t)(n & 63) * DIM + j);
    float4 a = s[0], b = s[1];
    float v[8] = {a.x, a.y, a.z, a.w, b.x, b.y, b.z, b.w};
    __half hv[8], lv[8];
#pragma unroll
    for (int i = 0; i < 8; i++) split_hl(v[i], hv[i], lv[i]);
    *(uint4*)(hi + (size_t)e0) = *(uint4*)hv;
    *(uint4*)(lo + (size_t)e0) = *(uint4*)lv;
}

// ---------------------------------------------------------------------------
// HMMA GEMM (unchanged from R12 measured build): CTA 256x128, warp tile 64x64.
// fp16 hi/lo 3-term split, fp32 accum, 3-stage cp.async pipeline.
// EPI 0: fp32 C. EPI 1: silu -> fp16 hi/lo.
// ---------------------------------------------------------------------------
template <int EPI>
__global__ __launch_bounds__(256)
void hgemm_kernel(const __half* __restrict__ Ahg,
                  const __half* __restrict__ Alg,
                  const __half* __restrict__ Bhg,
                  const __half* __restrict__ Blg,
                  float* __restrict__ Cf,
                  __half* __restrict__ Oh,
                  __half* __restrict__ Ol,
                  int N, int K) {
    extern __shared__ __align__(16) __half hsm[];
    const int tid  = threadIdx.x;
    const int wid  = tid >> 5, lane = tid & 31;
    const int wm   = wid >> 1, wn = wid & 1;          // 4 x 2 warp grid
    const int gr   = lane >> 2, gc2 = (lane & 3) * 2;
    const int bm0  = blockIdx.y * BM;
    const int bn0  = blockIdx.x * BN;

    const __half* gAh = Ahg + (size_t)bm0 * K;
    const __half* gAl = Alg + (size_t)bm0 * K;
    const __half* gBh = Bhg + (size_t)bn0 * K;
    const __half* gBl = Blg + (size_t)bn0 * K;

    const uint32_t smu = smem_u32(hsm);

    float acc[4][8][4];
#pragma unroll
    for (int mi = 0; mi < 4; mi++)
#pragma unroll
        for (int ni = 0; ni < 8; ni++)
#pragma unroll
            for (int j = 0; j < 4; j++) acc[mi][ni][j] = 0.0f;

    const int NKT = K >> 4;

    // stage layout: [Ah 256r][Al 256r][Bh 128r][Bl 128r], 48 B/row,
    // 32 B loaded per row per k-tile -> 1536 cp16 = 6 per thread.
    auto load_stage = [&](int s, int kt) {
        uint32_t sb = smu + s * STG_B;
#pragma unroll
        for (int j = 0; j < 6; j++) {
            int c = tid + j * 256;          // 0..1535
            int rowcat = c >> 1, ch = c & 1;
            const __half* gp;
            if (rowcat < 256)      gp = gAh + (size_t)rowcat * K;
            else if (rowcat < 512) gp = gAl + (size_t)(rowcat - 256) * K;
            else if (rowcat < 640) gp = gBh + (size_t)(rowcat - 512) * K;
            else                   gp = gBl + (size_t)(rowcat - 640) * K;
            gp += kt * BK + ch * 8;
            cp16(sb + rowcat * (LDSK * 2) + ch * 16, gp);
        }
    };

    load_stage(0, 0);
    asm volatile("cp.async.commit_group;");
    load_stage(1, 1);
    asm volatile("cp.async.commit_group;");

    for (int kt = 0; kt < NKT; kt++) {
        asm volatile("cp.async.wait_group 1;");
        __syncthreads();

        if (kt + 2 < NKT) load_stage((kt + 2) % 3, kt + 2);
        asm volatile("cp.async.commit_group;");

        uint32_t sA  = smu + (kt % 3) * STG_B;       // Ah
        uint32_t sAl = sA + AT_B;
        uint32_t sBh = sA + 2 * AT_B;
        uint32_t sBl = sA + 2 * AT_B + BT_B;

        uint32_t a[4][4], bh[8][2];
        // keep all Bh fragments live (reused by Al*Bh)
#pragma unroll
        for (int ni = 0; ni < 8; ni++) {
            uint32_t off = ((wn * 64 + ni * 8 + gr) * LDSK + gc2) * 2;
            bh[ni][0] = lds32(sBh + off);
            bh[ni][1] = lds32(sBh + off + 16);
        }
        // a <- Ah
#pragma unroll
        for (int mi = 0; mi < 4; mi++) {
            uint32_t base = sA + ((wm * 64 + mi * 16 + gr) * LDSK + gc2) * 2;
            a[mi][0] = lds32(base);
            a[mi][1] = lds32(base + 8 * LDSK * 2);
            a[mi][2] = lds32(base + 16);
            a[mi][3] = lds32(base + 8 * LDSK * 2 + 16);
        }
        // Ah * Bh
#pragma unroll
        for (int mi = 0; mi < 4; mi++)
#pragma unroll
            for (int ni = 0; ni < 8; ni++)
                mma16816(acc[mi][ni], a[mi], bh[ni]);
        // Ah * Bl (transient bl fragments)
#pragma unroll
        for (int ni = 0; ni < 8; ni++) {
            uint32_t off = ((wn * 64 + ni * 8 + gr) * LDSK + gc2) * 2;
            uint32_t bl[2];
            bl[0] = lds32(sBl + off);
            bl[1] = lds32(sBl + off + 16);
#pragma unroll
            for (int mi = 0; mi < 4; mi++)
                mma16816(acc[mi][ni], a[mi], bl);
        }
        // a <- Al, then Al * Bh
#pragma unroll
        for (int mi = 0; mi < 4; mi++) {
            uint32_t base = sAl + ((wm * 64 + mi * 16 + gr) * LDSK + gc2) * 2;
            a[mi][0] = lds32(base);
            a[mi][1] = lds32(base + 8 * LDSK * 2);
            a[mi][2] = lds32(base + 16);
            a[mi][3] = lds32(base + 8 * LDSK * 2 + 16);
        }
#pragma unroll
        for (int mi = 0; mi < 4; mi++)
#pragma unroll
            for (int ni = 0; ni < 8; ni++)
                mma16816(acc[mi][ni], a[mi], bh[ni]);
    }

    // ---- epilogue ----
#pragma unroll
    for (int mi = 0; mi < 4; mi++) {
        int r0 = bm0 + wm * 64 + mi * 16 + gr;
#pragma unroll
        for (int ni = 0; ni < 8; ni++) {
            int col = bn0 + wn * 64 + ni * 8 + gc2;
            float* c = acc[mi][ni];
            if (EPI == 0) {
                *(float2*)&Cf[(size_t)r0 * N + col]       = make_float2(c[0], c[1]);
                *(float2*)&Cf[(size_t)(r0 + 8) * N + col] = make_float2(c[2], c[3]);
            } else {
                float s0 = c[0] * fast_sigmoid(c[0]);
                float s1 = c[1] * fast_sigmoid(c[1]);
                float s2 = c[2] * fast_sigmoid(c[2]);
                float s3 = c[3] * fast_sigmoid(c[3]);
                __half h0, l0, h1, l1, h2, l2, h3, l3;
                split_hl(s0, h0, l0); split_hl(s1, h1, l1);
                split_hl(s2, h2, l2); split_hl(s3, h3, l3);
                __half2 ph0; ph0.x = h0; ph0.y = h1;
                __half2 pl0; pl0.x = l0; pl0.y = l1;
                __half2 ph1; ph1.x = h2; ph1.y = h3;
                __half2 pl1; pl1.x = l2; pl1.y = l3;
                *(__half2*)&Oh[(size_t)r0 * N + col]       = ph0;
                *(__half2*)&Ol[(size_t)r0 * N + col]       = pl0;
                *(__half2*)&Oh[(size_t)(r0 + 8) * N + col] = ph1;
                *(__half2*)&Ol[(size_t)(r0 + 8) * N + col] = pl1;
            }
        }
    }
}

// ---------------------------------------------------------------------------
// GEMM3 (K=64): fp32 FFMA2 SGEMM  C[M,N] = A[M,K] * B[N,K]^T  (proven kernel)
// ---------------------------------------------------------------------------
__global__ __launch_bounds__(256, 2)
void sgemm_kernel(const float* __restrict__ A,
                  const float* __restrict__ B,
                  float* __restrict__ C,
                  int M, int N, int K) {
    __shared__ float As[2][8][128];
    __shared__ float Bs[2][8][128];

    const int tid = threadIdx.x;
    const int tx  = tid & 15;
    const int ty  = tid >> 4;
    const int bm0 = blockIdx.y * 128;
    const int bn0 = blockIdx.x * 128;
    const int lr = tid >> 1;
    const int lk = (tid & 1) * 4;

    const float* Aptr = A + (size_t)(bm0 + lr) * K + lk;
    const float* Bptr = B + (size_t)(bn0 + lr) * K + lk;

    unsigned long long acc[8][4];
#pragma unroll
    for (int i = 0; i < 8; i++)
#pragma unroll
        for (int j = 0; j < 4; j++) acc[i][j] = 0ULL;

    const int NIT = K >> 3;
    {
        float4 av = *(const float4*)Aptr;
        float4 bv = *(const float4*)Bptr;
        As[0][lk + 0][lr] = av.x; As[0][lk + 1][lr] = av.y;
        As[0][lk + 2][lr] = av.z; As[0][lk + 3][lr] = av.w;
        Bs[0][lk + 0][lr] = bv.x; Bs[0][lk + 1][lr] = bv.y;
        Bs[0][lk + 2][lr] = bv.z; Bs[0][lk + 3][lr] = bv.w;
    }
    __syncthreads();

    int buf = 0;
    for (int it = 0; it < NIT; ++it) {
        float4 an, bn_;
        const bool pf = (it + 1 < NIT);
        if (pf) {
            an  = *(const float4*)(Aptr + (size_t)(it + 1) * 8);
            bn_ = *(const float4*)(Bptr + (size_t)(it + 1) * 8);
        }
#pragma unroll
        for (int k = 0; k < 8; k++) {
            float4 a0 = *(const float4*)&As[buf][k][ty * 4];
            float4 a1 = *(const float4*)&As[buf][k][ty * 4 + 64];
            float4 b0 = *(const float4*)&Bs[buf][k][tx * 4];
            float4 b1 = *(const float4*)&Bs[buf][k][tx * 4 + 64];
            unsigned long long bp[4];
            bp[0] = ((const unsigned long long*)&b0)[0];
            bp[1] = ((const unsigned long long*)&b0)[1];
            bp[2] = ((const unsigned long long*)&b1)[0];
            bp[3] = ((const unsigned long long*)&b1)[1];
            float ar[8] = {a0.x, a0.y, a0.z, a0.w, a1.x, a1.y, a1.z, a1.w};
#pragma unroll
            for (int i = 0; i < 8; i++) {
                unsigned long long ap = splat2(ar[i]);
#pragma unroll
                for (int j = 0; j < 4; j++) ffma2(acc[i][j], ap, bp[j]);
            }
        }
        if (pf) {
            int nb2 = buf ^ 1;
            As[nb2][lk + 0][lr] = an.x;  As[nb2][lk + 1][lr] = an.y;
            As[nb2][lk + 2][lr] = an.z;  As[nb2][lk + 3][lr] = an.w;
            Bs[nb2][lk + 0][lr] = bn_.x; Bs[nb2][lk + 1][lr] = bn_.y;
            Bs[nb2][lk + 2][lr] = bn_.z; Bs[nb2][lk + 3][lr] = bn_.w;
        }
        __syncthreads();
        buf ^= 1;
    }

#pragma unroll
    for (int i = 0; i < 8; i++) {
        int rloc = (i < 4) ? (ty * 4 + i) : (64 + ty * 4 + (i - 4));
        int m = bm0 + rloc;
        float v[8];
#pragma unroll
        for (int j = 0; j < 4; j++) {
            v[2 * j]     = __uint_as_float((unsigned)(acc[i][j]));
            v[2 * j + 1] = __uint_as_float((unsigned)(acc[i][j] >> 32));
        }
        float* cp = C + (size_t)m * N + bn0;
        *(float4*)(cp + tx * 4)      = make_float4(v[0], v[1], v[2], v[3]);
        *(float4*)(cp + 64 + tx * 4) = make_float4(v[4], v[5], v[6], v[7]);
    }
}

// ---------------------------------------------------------------------------
// Sequential gated scan, ROW-SPLIT + CHAIN-DECOUPLED.
// 128 CTAs x 32 threads; CTA = (batch, 8-row block); lane = (rloc, h),
// h*16 columns per lane.
//
// Algebraic pipelining: with S_t = a_t S_{t-1} + c_t k_t (c_t = (1-a_t)v_t),
//   retrieved_t = S_{t-1}.k_t = a_{t-1}(S_{t-2}.k_t) + c_{t-1}(k_{t-1}.k_t)
//   o_t         = S_t.q_t     = a_t(S_{t-1}.q_t)     + c_t(k_t.q_t)
// so all 64-wide dots (P,Q,R,W) use >=1-step-stale state and sit OFF the
// serial chain; the chain is only  a -> 2 FMA -> sigmoid -> a.
// Loop invariant at entry of step t: S = S_{t-2}, kp = k_{t-1}, ap/cp gates.
// ---------------------------------------------------------------------------
#define SCH 16

__global__ __launch_bounds__(32, 1)
void scan_kernel(const float* __restrict__ kvqa,
                 const float* __restrict__ d_alpha,
                 const float* __restrict__ b_alpha,
                 float* __restrict__ cell,
                 float* __restrict__ S_out) {
    __shared__ float buf[2][SCH * 256];
    __shared__ float osm[SCH * 8];

    const int b    = blockIdx.x >> 3;
    const int rb   = blockIdx.x & 7;
    const int lane = threadIdx.x;
    const int rloc = lane >> 2;         // 0..7
    const int r    = rb * 8 + rloc;     // global state row
    const int h    = lane & 3;
    const int c0   = h * 16;

    float S[16], kp[16];
#pragma unroll
    for (int j = 0; j < 16; j++) { S[j] = 0.0f; kp[j] = 0.0f; }
    float ap = 0.0f, cp = 0.0f;

    const float dA = d_alpha[r];
    const float bA = b_alpha[r];

    const float* gsrc = kvqa + (size_t)b * TT * 256;

    {
        unsigned sa = (unsigned)__cvta_generic_to_shared(&buf[0][0]);
        for (int i = lane; i < SCH * 64; i += 32)
            cp16(sa + i * 16, gsrc + (size_t)i * 4);
        asm volatile("cp.async.commit_group;");
    }

    const int NCH = TT / SCH;   // 128
    for (int c = 0; c < NCH; ++c) {
        asm volatile("cp.async.wait_group 0;");
        __syncthreads();

        if (c + 1 < NCH) {
            unsigned sa = (unsigned)__cvta_generic_to_shared(&buf[(c + 1) & 1][0]);
            const float* g = gsrc + (size_t)(c + 1) * SCH * 256;
            for (int i = lane; i < SCH * 64; i += 32)
                cp16(sa + i * 16, g + (size_t)i * 4);
            asm volatile("cp.async.commit_group;");
        }

        const float* cb = &buf[c & 1][0];
#pragma unroll 1
        for (int s = 0; s < SCH; ++s) {
            const float* p = cb + s * 256;

            float4 k4[4], q4[4];
            const float4* kptr = (const float4*)(p + c0);
            const float4* qptr = (const float4*)(p + 128 + c0);
#pragma unroll
            for (int i = 0; i < 4; i++) { k4[i] = kptr[i]; q4[i] = qptr[i]; }
            float axv = p[192 + r];
            float vv  = p[64 + r];

            // ---- off-chain dots on stale state ----
            // P = S_{t-2}.k_t   Q = k_{t-1}.k_t
            float P0 = 0.f, P1 = 0.f, P2 = 0.f, P3 = 0.f;
            float Q0 = 0.f, Q1 = 0.f, Q2 = 0.f, Q3 = 0.f;
#pragma unroll
            for (int i = 0; i < 4; i++) {
                P0 = fmaf(S[4*i+0], k4[i].x, P0);
                P1 = fmaf(S[4*i+1], k4[i].y, P1);
                P2 = fmaf(S[4*i+2], k4[i].z, P2);
                P3 = fmaf(S[4*i+3], k4[i].w, P3);
                Q0 = fmaf(kp[4*i+0], k4[i].x, Q0);
                Q1 = fmaf(kp[4*i+1], k4[i].y, Q1);
                Q2 = fmaf(kp[4*i+2], k4[i].z, Q2);
                Q3 = fmaf(kp[4*i+3], k4[i].w, Q3);
            }
            float P = (P0 + P1) + (P2 + P3);
            float Q = (Q0 + Q1) + (Q2 + Q3);
            P += __shfl_xor_sync(0xffffffffu, P, 1);
            P += __shfl_xor_sync(0xffffffffu, P, 2);
            Q += __shfl_xor_sync(0xffffffffu, Q, 1);
            Q += __shfl_xor_sync(0xffffffffu, Q, 2);

            // ---- lagged state update: S <- S_{t-1} (uses OLD gates) ----
            // also W = k_t.q_t and R = S_{t-1}.q_t
            float R0 = 0.f, R1 = 0.f, R2 = 0.f, R3 = 0.f;
            float W0 = 0.f, W1 = 0.f, W2 = 0.f, W3 = 0.f;
#pragma unroll
            for (int i = 0; i < 4; i++) {
                S[4*i+0] = fmaf(ap, S[4*i+0], cp * kp[4*i+0]);
                S[4*i+1] = fmaf(ap, S[4*i+1], cp * kp[4*i+1]);
                S[4*i+2] = fmaf(ap, S[4*i+2], cp * kp[4*i+2]);
                S[4*i+3] = fmaf(ap, S[4*i+3], cp * kp[4*i+3]);
                R0 = fmaf(S[4*i+0], q4[i].x, R0);
                R1 = fmaf(S[4*i+1], q4[i].y, R1);
                R2 = fmaf(S[4*i+2], q4[i].z, R2);
                R3 = fmaf(S[4*i+3], q4[i].w, R3);
                W0 = fmaf(k4[i].x, q4[i].x, W0);
                W1 = fmaf(k4[i].y, q4[i].y, W1);
                W2 = fmaf(k4[i].z, q4[i].z, W2);
                W3 = fmaf(k4[i].w, q4[i].w, W3);
            }
            float R = (R0 + R1) + (R2 + R3);
            float W = (W0 + W1) + (W2 + W3);
            R += __shfl_xor_sync(0xffffffffu, R, 1);
            R += __shfl_xor_sync(0xffffffffu, R, 2);
            W += __shfl_xor_sync(0xffffffffu, W, 1);
            W += __shfl_xor_sync(0xffffffffu, W, 2);

            // ---- serial chain: 2 FMA + sigmoid ----
            float retrieved = fmaf(ap, P, cp * Q);
            float araw = fmaf(dA, retrieved, axv + bA);
            float al   = fast_sigmoid(araw);
            float cc   = (1.0f - al) * vv;

            // o_t = al*R + cc*W ; out = o * silu(o)
            float o = fmaf(al, R, cc * W);
            if (h == 0) {
                float sg = fast_sigmoid(o);
                osm[s * 8 + rloc] = o * o * sg;
            }

            // carry: kp <- k_t, gates
#pragma unroll
            for (int i = 0; i < 4; i++) {
                kp[4*i+0] = k4[i].x; kp[4*i+1] = k4[i].y;
                kp[4*i+2] = k4[i].z; kp[4*i+3] = k4[i].w;
            }
            ap = al; cp = cc;
        }
        __syncthreads();

        // dump chunk outputs: 16 steps x 8 rows
        {
            float* gout = cell + ((size_t)b * TT + (size_t)c * SCH) * NST + rb * 8;
#pragma unroll
            for (int i = lane; i < SCH * 8; i += 32) {
                int s = i >> 3, rr = i & 7;
                gout[(size_t)s * NST + rr] = osm[i];
            }
        }
    }

    // trailing update: S currently = S_{TT-2}; apply last gates -> S_{TT-1}
#pragma unroll
    for (int j = 0; j < 16; j++) S[j] = fmaf(ap, S[j], cp * kp[j]);

    float* sp = S_out + (size_t)b * (NST * NST) + (size_t)r * NST + c0;
#pragma unroll
    for (int i = 0; i < 4; i++)
        ((float4*)sp)[i] = make_float4(S[4*i+0], S[4*i+1], S[4*i+2], S[4*i+3]);
}

// ---------------------------------------------------------------------------
// Launch
// ---------------------------------------------------------------------------
extern "C" void kernel_launch(void* const* d_in, const int* in_sizes, int n_in,
                              void* d_out, int out_size) {
    const float* x   = (const float*)d_in[0];
    const float* Win = (const float*)d_in[1];
    const float* Wk  = (const float*)d_in[2];
    const float* Wv  = (const float*)d_in[3];
    const float* Wq  = (const float*)d_in[4];
    const float* Wa  = (const float*)d_in[5];
    const float* dAl = (const float*)d_in[6];
    const float* bAl = (const float*)d_in[7];
    const float* Wout= (const float*)d_in[8];
    float* out = (float*)d_out;

    void *xhh_v, *xhl_v, *xph_v, *xpl_v, *wih_v, *wil_v, *wch_v, *wcl_v,
         *kvqa_v, *cell_v;
    cudaGetSymbolAddress(&xhh_v, g_xhh);  cudaGetSymbolAddress(&xhl_v, g_xhl);
    cudaGetSymbolAddress(&xph_v, g_xph);  cudaGetSymbolAddress(&xpl_v, g_xpl);
    cudaGetSymbolAddress(&wih_v, g_wih);  cudaGetSymbolAddress(&wil_v, g_wil);
    cudaGetSymbolAddress(&wch_v, g_wch);  cudaGetSymbolAddress(&wcl_v, g_wcl);
    cudaGetSymbolAddress(&kvqa_v, g_kvqa);
    cudaGetSymbolAddress(&cell_v, g_cell);
    __half* xhh = (__half*)xhh_v;  __half* xhl = (__half*)xhl_v;
    __half* xph = (__half*)xph_v;  __half* xpl = (__half*)xpl_v;
    __half* wih = (__half*)wih_v;  __half* wil = (__half*)wil_v;
    __half* wch = (__half*)wch_v;  __half* wcl = (__half*)wcl_v;
    float* kvqa = (float*)kvqa_v;
    float* cell = (float*)cell_v;

    cudaFuncSetAttribute(hgemm_kernel<0>,
                         cudaFuncAttributeMaxDynamicSharedMemorySize, SMEM_H);
    cudaFuncSetAttribute(hgemm_kernel<1>,
                         cudaFuncAttributeMaxDynamicSharedMemorySize, SMEM_H);

    // 0) conversions to fp16 hi/lo
    conv_hl_kernel<<<(MTOT * DIM / 8 + 255) / 256, 256>>>(x, xhh, xhl,
                                                          MTOT * DIM / 8);
    conv_hl_kernel<<<(DIM * DIM / 8 + 255) / 256, 256>>>(Win, wih, wil,
                                                         DIM * DIM / 8);
    conv_wcat_kernel<<<(256 * DIM / 8 + 255) / 256, 256>>>(Wk, Wv, Wq, Wa,
                                                           wch, wcl);

    // 1) xp = silu(x @ W_in^T)  (M=32768, N=1024, K=1024) -> fp16 hi/lo
    hgemm_kernel<1><<<dim3(DIM / BN, MTOT / BM), 256, SMEM_H>>>(
        xhh, xhl, wih, wil, nullptr, xph, xpl, DIM, DIM);

    // 2) kvqa = xp @ Wcat^T  (M=32768, N=256, K=1024) -> fp32
    hgemm_kernel<0><<<dim3(256 / BN, MTOT / BM), 256, SMEM_H>>>(
        xph, xpl, wch, wcl, kvqa, nullptr, nullptr, 256, DIM);

    // 3) chain-decoupled row-split scan (also writes S_final to d_out tail)
    scan_kernel<<<BB * 8, 32>>>(kvqa, dAl, bAl, cell, out + (size_t)MTOT * DIM);

    // 4) output = cell @ W_out^T  (M=32768, N=1024, K=64)
    sgemm_kernel<<<dim3(DIM / 128, MTOT / 128), 256>>>(
        cell, Wout, out, MTOT, DIM, NST);
}

// round 15
// speedup vs baseline: 1.0209x; 1.0209x over previous
#include <cuda_runtime.h>
#include <cuda_fp16.h>
#include <cuda_bf16.h>
#include <cstdint>

// ---------------------------------------------------------------------------
// Problem constants
// ---------------------------------------------------------------------------
#define BB    16
#define TT    2048
#define DIM   1024
#define NST   64
#define MTOT  (BB * TT)          // 32768 rows

// HMMA GEMM tiling: CTA tile 256x128, warp tile 64x64 (8 warps, 4x2)
#define BM    256
#define BN    128
#define BK    16
#define LDSK  24                 // padded halves per smem row (48B)
#define AT_B  (256 * LDSK * 2)   // 12288 B  (Ah or Al tile)
#define BT_B  (128 * LDSK * 2)   // 6144 B   (Bh or Bl tile)
#define STG_B (2 * AT_B + 2 * BT_B)   // 36864 B per stage
#define SMEM_H (3 * STG_B)            // 110592 B (3 stages)

// ---------------------------------------------------------------------------
// Scratch (__device__ globals — no allocation allowed)
// ---------------------------------------------------------------------------
__device__ __align__(16) __half g_xhh[(size_t)MTOT * DIM];  // x hi
__device__ __align__(16) __half g_xhl[(size_t)MTOT * DIM];  // x lo
__device__ __align__(16) __half g_xph[(size_t)MTOT * DIM];  // xp hi
__device__ __align__(16) __half g_xpl[(size_t)MTOT * DIM];  // xp lo
__device__ __align__(16) __half g_wih[(size_t)DIM * DIM];   // W_in hi
__device__ __align__(16) __half g_wil[(size_t)DIM * DIM];   // W_in lo
__device__ __align__(16) __half g_wch[(size_t)256 * DIM];   // wcat hi
__device__ __align__(16) __half g_wcl[(size_t)256 * DIM];   // wcat lo
__device__ float g_kvqa[(size_t)MTOT * 256];   // 32 MB : [m][k|v|q|ax]
__device__ float g_cell[(size_t)MTOT * NST];   //  8 MB : gated cell output

// ---------------------------------------------------------------------------
// Helpers
// ---------------------------------------------------------------------------
__device__ __forceinline__ float fast_sigmoid(float x) {
    return __fdividef(1.0f, 1.0f + __expf(-x));
}

__device__ __forceinline__ uint32_t smem_u32(const void* p) {
    uint32_t a;
    asm("{ .reg .u64 t; cvta.to.shared.u64 t, %1; cvt.u32.u64 %0, t; }"
        : "=r"(a) : "l"(p));
    return a;
}

__device__ __forceinline__ void cp16(uint32_t dst, const void* src) {
    asm volatile("cp.async.cg.shared.global [%0], [%1], 16;"
                 :: "r"(dst), "l"(src));
}

__device__ __forceinline__ uint32_t lds32(uint32_t a) {
    uint32_t v;
    asm("ld.shared.b32 %0, [%1];" : "=r"(v) : "r"(a));
    return v;
}

__device__ __forceinline__ void mma16816(float* c, const uint32_t* a,
                                         const uint32_t* b) {
    asm volatile(
        "mma.sync.aligned.m16n8k16.row.col.f32.f16.f16.f32 "
        "{%0,%1,%2,%3}, {%4,%5,%6,%7}, {%8,%9}, {%0,%1,%2,%3};"
        : "+f"(c[0]), "+f"(c[1]), "+f"(c[2]), "+f"(c[3])
        : "r"(a[0]), "r"(a[1]), "r"(a[2]), "r"(a[3]), "r"(b[0]), "r"(b[1]));
}

__device__ __forceinline__ void ffma2(unsigned long long &acc,
                                      unsigned long long a,
                                      unsigned long long b) {
    asm("fma.rn.f32x2 %0, %1, %2, %0;" : "+l"(acc) : "l"(a), "l"(b));
}
__device__ __forceinline__ unsigned long long splat2(float v) {
    unsigned long long r;
    asm("mov.b64 %0, {%1, %1};" : "=l"(r) : "r"(__float_as_uint(v)));
    return r;
}

__device__ __forceinline__ void split_hl(float v, __half& h, __half& l) {
    h = __float2half_rn(v);
    l = __float2half_rn(v - __half2float(h));
}

// ---------------------------------------------------------------------------
// Conversion kernels: fp32 -> fp16 hi/lo, row-major, 8 elems per thread
// ---------------------------------------------------------------------------
__global__ void conv_hl_kernel(const float* __restrict__ src,
                               __half* __restrict__ hi,
                               __half* __restrict__ lo, int n8) {
    int t = blockIdx.x * blockDim.x + threadIdx.x;
    if (t >= n8) return;
    const float4* s = (const float4*)(src + (size_t)t * 8);
    float4 a = s[0], b = s[1];
    float v[8] = {a.x, a.y, a.z, a.w, b.x, b.y, b.z, b.w};
    __half hv[8], lv[8];
#pragma unroll
    for (int i = 0; i < 8; i++) split_hl(v[i], hv[i], lv[i]);
    *(uint4*)(hi + (size_t)t * 8) = *(uint4*)hv;
    *(uint4*)(lo + (size_t)t * 8) = *(uint4*)lv;
}

// wcat = concat(W_k,W_v,W_q,W_alpha)[256][1024] -> hi/lo
__global__ void conv_wcat_kernel(const float* __restrict__ Wk,
                                 const float* __restrict__ Wv,
                                 const float* __restrict__ Wq,
                                 const float* __restrict__ Wa,
                                 __half* __restrict__ hi,
                                 __half* __restrict__ lo) {
    int t = blockIdx.x * blockDim.x + threadIdx.x;   // 32768 threads
    if (t >= 256 * DIM / 8) return;
    int e0 = t * 8;
    int n = e0 >> 10;
    int j = e0 & 1023;
    const float* src = (n < 64) ? Wk : (n < 128) ? Wv : (n < 192) ? Wq : Wa;
    const float4* s = (const float4*)(src + (size_t)(n & 63) * DIM + j);
    float4 a = s[0], b = s[1];
    float v[8] = {a.x, a.y, a.z, a.w, b.x, b.y, b.z, b.w};
    __half hv[8], lv[8];
#pragma unroll
    for (int i = 0; i < 8; i++) split_hl(v[i], hv[i], lv[i]);
    *(uint4*)(hi + (size_t)e0) = *(uint4*)hv;
    *(uint4*)(lo + (size_t)e0) = *(uint4*)lv;
}

// ---------------------------------------------------------------------------
// HMMA GEMM (unchanged from R12 measured build): CTA 256x128, warp tile 64x64.
// fp16 hi/lo 3-term split, fp32 accum, 3-stage cp.async pipeline.
// EPI 0: fp32 C. EPI 1: silu -> fp16 hi/lo.
// ---------------------------------------------------------------------------
template <int EPI>
__global__ __launch_bounds__(256)
void hgemm_kernel(const __half* __restrict__ Ahg,
                  const __half* __restrict__ Alg,
                  const __half* __restrict__ Bhg,
                  const __half* __restrict__ Blg,
                  float* __restrict__ Cf,
                  __half* __restrict__ Oh,
                  __half* __restrict__ Ol,
                  int N, int K) {
    extern __shared__ __align__(16) __half hsm[];
    const int tid  = threadIdx.x;
    const int wid  = tid >> 5, lane = tid & 31;
    const int wm   = wid >> 1, wn = wid & 1;          // 4 x 2 warp grid
    const int gr   = lane >> 2, gc2 = (lane & 3) * 2;
    const int bm0  = blockIdx.y * BM;
    const int bn0  = blockIdx.x * BN;

    const __half* gAh = Ahg + (size_t)bm0 * K;
    const __half* gAl = Alg + (size_t)bm0 * K;
    const __half* gBh = Bhg + (size_t)bn0 * K;
    const __half* gBl = Blg + (size_t)bn0 * K;

    const uint32_t smu = smem_u32(hsm);

    float acc[4][8][4];
#pragma unroll
    for (int mi = 0; mi < 4; mi++)
#pragma unroll
        for (int ni = 0; ni < 8; ni++)
#pragma unroll
            for (int j = 0; j < 4; j++) acc[mi][ni][j] = 0.0f;

    const int NKT = K >> 4;

    // stage layout: [Ah 256r][Al 256r][Bh 128r][Bl 128r], 48 B/row,
    // 32 B loaded per row per k-tile -> 1536 cp16 = 6 per thread.
    auto load_stage = [&](int s, int kt) {
        uint32_t sb = smu + s * STG_B;
#pragma unroll
        for (int j = 0; j < 6; j++) {
            int c = tid + j * 256;          // 0..1535
            int rowcat = c >> 1, ch = c & 1;
            const __half* gp;
            if (rowcat < 256)      gp = gAh + (size_t)rowcat * K;
            else if (rowcat < 512) gp = gAl + (size_t)(rowcat - 256) * K;
            else if (rowcat < 640) gp = gBh + (size_t)(rowcat - 512) * K;
            else                   gp = gBl + (size_t)(rowcat - 640) * K;
            gp += kt * BK + ch * 8;
            cp16(sb + rowcat * (LDSK * 2) + ch * 16, gp);
        }
    };

    load_stage(0, 0);
    asm volatile("cp.async.commit_group;");
    load_stage(1, 1);
    asm volatile("cp.async.commit_group;");

    for (int kt = 0; kt < NKT; kt++) {
        asm volatile("cp.async.wait_group 1;");
        __syncthreads();

        if (kt + 2 < NKT) load_stage((kt + 2) % 3, kt + 2);
        asm volatile("cp.async.commit_group;");

        uint32_t sA  = smu + (kt % 3) * STG_B;       // Ah
        uint32_t sAl = sA + AT_B;
        uint32_t sBh = sA + 2 * AT_B;
        uint32_t sBl = sA + 2 * AT_B + BT_B;

        uint32_t a[4][4], bh[8][2];
        // keep all Bh fragments live (reused by Al*Bh)
#pragma unroll
        for (int ni = 0; ni < 8; ni++) {
            uint32_t off = ((wn * 64 + ni * 8 + gr) * LDSK + gc2) * 2;
            bh[ni][0] = lds32(sBh + off);
            bh[ni][1] = lds32(sBh + off + 16);
        }
        // a <- Ah
#pragma unroll
        for (int mi = 0; mi < 4; mi++) {
            uint32_t base = sA + ((wm * 64 + mi * 16 + gr) * LDSK + gc2) * 2;
            a[mi][0] = lds32(base);
            a[mi][1] = lds32(base + 8 * LDSK * 2);
            a[mi][2] = lds32(base + 16);
            a[mi][3] = lds32(base + 8 * LDSK * 2 + 16);
        }
        // Ah * Bh
#pragma unroll
        for (int mi = 0; mi < 4; mi++)
#pragma unroll
            for (int ni = 0; ni < 8; ni++)
                mma16816(acc[mi][ni], a[mi], bh[ni]);
        // Ah * Bl (transient bl fragments)
#pragma unroll
        for (int ni = 0; ni < 8; ni++) {
            uint32_t off = ((wn * 64 + ni * 8 + gr) * LDSK + gc2) * 2;
            uint32_t bl[2];
            bl[0] = lds32(sBl + off);
            bl[1] = lds32(sBl + off + 16);
#pragma unroll
            for (int mi = 0; mi < 4; mi++)
                mma16816(acc[mi][ni], a[mi], bl);
        }
        // a <- Al, then Al * Bh
#pragma unroll
        for (int mi = 0; mi < 4; mi++) {
            uint32_t base = sAl + ((wm * 64 + mi * 16 + gr) * LDSK + gc2) * 2;
            a[mi][0] = lds32(base);
            a[mi][1] = lds32(base + 8 * LDSK * 2);
            a[mi][2] = lds32(base + 16);
            a[mi][3] = lds32(base + 8 * LDSK * 2 + 16);
        }
#pragma unroll
        for (int mi = 0; mi < 4; mi++)
#pragma unroll
            for (int ni = 0; ni < 8; ni++)
                mma16816(acc[mi][ni], a[mi], bh[ni]);
    }

    // ---- epilogue ----
#pragma unroll
    for (int mi = 0; mi < 4; mi++) {
        int r0 = bm0 + wm * 64 + mi * 16 + gr;
#pragma unroll
        for (int ni = 0; ni < 8; ni++) {
            int col = bn0 + wn * 64 + ni * 8 + gc2;
            float* c = acc[mi][ni];
            if (EPI == 0) {
                *(float2*)&Cf[(size_t)r0 * N + col]       = make_float2(c[0], c[1]);
                *(float2*)&Cf[(size_t)(r0 + 8) * N + col] = make_float2(c[2], c[3]);
            } else {
                float s0 = c[0] * fast_sigmoid(c[0]);
                float s1 = c[1] * fast_sigmoid(c[1]);
                float s2 = c[2] * fast_sigmoid(c[2]);
                float s3 = c[3] * fast_sigmoid(c[3]);
                __half h0, l0, h1, l1, h2, l2, h3, l3;
                split_hl(s0, h0, l0); split_hl(s1, h1, l1);
                split_hl(s2, h2, l2); split_hl(s3, h3, l3);
                __half2 ph0; ph0.x = h0; ph0.y = h1;
                __half2 pl0; pl0.x = l0; pl0.y = l1;
                __half2 ph1; ph1.x = h2; ph1.y = h3;
                __half2 pl1; pl1.x = l2; pl1.y = l3;
                *(__half2*)&Oh[(size_t)r0 * N + col]       = ph0;
                *(__half2*)&Ol[(size_t)r0 * N + col]       = pl0;
                *(__half2*)&Oh[(size_t)(r0 + 8) * N + col] = ph1;
                *(__half2*)&Ol[(size_t)(r0 + 8) * N + col] = pl1;
            }
        }
    }
}

// ---------------------------------------------------------------------------
// GEMM3 (K=64): fp32 FFMA2 SGEMM  C[M,N] = A[M,K] * B[N,K]^T  (proven kernel)
// ---------------------------------------------------------------------------
__global__ __launch_bounds__(256, 2)
void sgemm_kernel(const float* __restrict__ A,
                  const float* __restrict__ B,
                  float* __restrict__ C,
                  int M, int N, int K) {
    __shared__ float As[2][8][128];
    __shared__ float Bs[2][8][128];

    const int tid = threadIdx.x;
    const int tx  = tid & 15;
    const int ty  = tid >> 4;
    const int bm0 = blockIdx.y * 128;
    const int bn0 = blockIdx.x * 128;
    const int lr = tid >> 1;
    const int lk = (tid & 1) * 4;

    const float* Aptr = A + (size_t)(bm0 + lr) * K + lk;
    const float* Bptr = B + (size_t)(bn0 + lr) * K + lk;

    unsigned long long acc[8][4];
#pragma unroll
    for (int i = 0; i < 8; i++)
#pragma unroll
        for (int j = 0; j < 4; j++) acc[i][j] = 0ULL;

    const int NIT = K >> 3;
    {
        float4 av = *(const float4*)Aptr;
        float4 bv = *(const float4*)Bptr;
        As[0][lk + 0][lr] = av.x; As[0][lk + 1][lr] = av.y;
        As[0][lk + 2][lr] = av.z; As[0][lk + 3][lr] = av.w;
        Bs[0][lk + 0][lr] = bv.x; Bs[0][lk + 1][lr] = bv.y;
        Bs[0][lk + 2][lr] = bv.z; Bs[0][lk + 3][lr] = bv.w;
    }
    __syncthreads();

    int buf = 0;
    for (int it = 0; it < NIT; ++it) {
        float4 an, bn_;
        const bool pf = (it + 1 < NIT);
        if (pf) {
            an  = *(const float4*)(Aptr + (size_t)(it + 1) * 8);
            bn_ = *(const float4*)(Bptr + (size_t)(it + 1) * 8);
        }
#pragma unroll
        for (int k = 0; k < 8; k++) {
            float4 a0 = *(const float4*)&As[buf][k][ty * 4];
            float4 a1 = *(const float4*)&As[buf][k][ty * 4 + 64];
            float4 b0 = *(const float4*)&Bs[buf][k][tx * 4];
            float4 b1 = *(const float4*)&Bs[buf][k][tx * 4 + 64];
            unsigned long long bp[4];
            bp[0] = ((const unsigned long long*)&b0)[0];
            bp[1] = ((const unsigned long long*)&b0)[1];
            bp[2] = ((const unsigned long long*)&b1)[0];
            bp[3] = ((const unsigned long long*)&b1)[1];
            float ar[8] = {a0.x, a0.y, a0.z, a0.w, a1.x, a1.y, a1.z, a1.w};
#pragma unroll
            for (int i = 0; i < 8; i++) {
                unsigned long long ap = splat2(ar[i]);
#pragma unroll
                for (int j = 0; j < 4; j++) ffma2(acc[i][j], ap, bp[j]);
            }
        }
        if (pf) {
            int nb2 = buf ^ 1;
            As[nb2][lk + 0][lr] = an.x;  As[nb2][lk + 1][lr] = an.y;
            As[nb2][lk + 2][lr] = an.z;  As[nb2][lk + 3][lr] = an.w;
            Bs[nb2][lk + 0][lr] = bn_.x; Bs[nb2][lk + 1][lr] = bn_.y;
            Bs[nb2][lk + 2][lr] = bn_.z; Bs[nb2][lk + 3][lr] = bn_.w;
        }
        __syncthreads();
        buf ^= 1;
    }

#pragma unroll
    for (int i = 0; i < 8; i++) {
        int rloc = (i < 4) ? (ty * 4 + i) : (64 + ty * 4 + (i - 4));
        int m = bm0 + rloc;
        float v[8];
#pragma unroll
        for (int j = 0; j < 4; j++) {
            v[2 * j]     = __uint_as_float((unsigned)(acc[i][j]));
            v[2 * j + 1] = __uint_as_float((unsigned)(acc[i][j] >> 32));
        }
        float* cp = C + (size_t)m * N + bn0;
        *(float4*)(cp + tx * 4)      = make_float4(v[0], v[1], v[2], v[3]);
        *(float4*)(cp + 64 + tx * 4) = make_float4(v[4], v[5], v[6], v[7]);
    }
}

// ---------------------------------------------------------------------------
// Sequential gated scan, FINE ROW-SPLIT: 256 CTAs x 32 threads (~2 warps/SM
// for latency interleaving). CTA = (batch, 4-row block). Lane: rloc = lane>>3
// (0..3), h = lane&7 -> 8 S-columns per lane. Reductions: 3 shuffles (xor
// 1,2,4 over the 8 lanes of a row).
// ---------------------------------------------------------------------------
#define SCH 16

__global__ __launch_bounds__(32, 2)
void scan_kernel(const float* __restrict__ kvqa,
                 const float* __restrict__ d_alpha,
                 const float* __restrict__ b_alpha,
                 float* __restrict__ cell,
                 float* __restrict__ S_out) {
    __shared__ float buf[2][SCH * 256];
    __shared__ float osm[SCH * 4];

    const int b    = blockIdx.x >> 4;
    const int rb   = blockIdx.x & 15;
    const int lane = threadIdx.x;
    const int rloc = lane >> 3;         // 0..3
    const int r    = rb * 4 + rloc;     // global state row
    const int h    = lane & 7;
    const int c0   = h * 8;

    float S[8];
#pragma unroll
    for (int j = 0; j < 8; j++) S[j] = 0.0f;

    const float dA = d_alpha[r];
    const float bA = b_alpha[r];

    const float* gsrc = kvqa + (size_t)b * TT * 256;

    {
        unsigned sa = (unsigned)__cvta_generic_to_shared(&buf[0][0]);
        for (int i = lane; i < SCH * 64; i += 32)
            cp16(sa + i * 16, gsrc + (size_t)i * 4);
        asm volatile("cp.async.commit_group;");
    }

    const int NCH = TT / SCH;   // 128
    for (int c = 0; c < NCH; ++c) {
        asm volatile("cp.async.wait_group 0;");
        __syncthreads();

        if (c + 1 < NCH) {
            unsigned sa = (unsigned)__cvta_generic_to_shared(&buf[(c + 1) & 1][0]);
            const float* g = gsrc + (size_t)(c + 1) * SCH * 256;
            for (int i = lane; i < SCH * 64; i += 32)
                cp16(sa + i * 16, g + (size_t)i * 4);
            asm volatile("cp.async.commit_group;");
        }

        const float* cb = &buf[c & 1][0];
#pragma unroll 2
        for (int s = 0; s < SCH; ++s) {
            const float* p = cb + s * 256;

            float4 k4[2];
            const float4* kp = (const float4*)(p + c0);
            k4[0] = kp[0]; k4[1] = kp[1];

            float r0, r1, r2, r3;
            r0 = S[0] * k4[0].x; r1 = S[1] * k4[0].y;
            r2 = S[2] * k4[0].z; r3 = S[3] * k4[0].w;
            r0 = fmaf(S[4], k4[1].x, r0);
            r1 = fmaf(S[5], k4[1].y, r1);
            r2 = fmaf(S[6], k4[1].z, r2);
            r3 = fmaf(S[7], k4[1].w, r3);
            float rp = (r0 + r1) + (r2 + r3);
            rp += __shfl_xor_sync(0xffffffffu, rp, 1);
            rp += __shfl_xor_sync(0xffffffffu, rp, 2);
            rp += __shfl_xor_sync(0xffffffffu, rp, 4);

            float axv = p[192 + r];
            float vv  = p[64 + r];
            float araw = fmaf(dA, rp, axv + bA);
            float al   = fast_sigmoid(araw);
            float cc   = (1.0f - al) * vv;

            float4 q4[2];
            const float4* qp = (const float4*)(p + 128 + c0);
            q4[0] = qp[0]; q4[1] = qp[1];

            float o0, o1, o2, o3;
            S[0] = fmaf(al, S[0], cc * k4[0].x);
            S[1] = fmaf(al, S[1], cc * k4[0].y);
            S[2] = fmaf(al, S[2], cc * k4[0].z);
            S[3] = fmaf(al, S[3], cc * k4[0].w);
            o0 = S[0] * q4[0].x; o1 = S[1] * q4[0].y;
            o2 = S[2] * q4[0].z; o3 = S[3] * q4[0].w;
            S[4] = fmaf(al, S[4], cc * k4[1].x);
            S[5] = fmaf(al, S[5], cc * k4[1].y);
            S[6] = fmaf(al, S[6], cc * k4[1].z);
            S[7] = fmaf(al, S[7], cc * k4[1].w);
            o0 = fmaf(S[4], q4[1].x, o0);
            o1 = fmaf(S[5], q4[1].y, o1);
            o2 = fmaf(S[6], q4[1].z, o2);
            o3 = fmaf(S[7], q4[1].w, o3);
            float o = (o0 + o1) + (o2 + o3);
            o += __shfl_xor_sync(0xffffffffu, o, 1);
            o += __shfl_xor_sync(0xffffffffu, o, 2);
            o += __shfl_xor_sync(0xffffffffu, o, 4);

            if (h == 0) {
                float sg = fast_sigmoid(o);
                osm[s * 4 + rloc] = o * o * sg;   // o * silu(o)
            }
        }
        __syncthreads();

        // dump chunk outputs: 16 steps x 4 rows = 64 floats
        {
            float* gout = cell + ((size_t)b * TT + (size_t)c * SCH) * NST + rb * 4;
#pragma unroll
            for (int i = lane; i < SCH * 4; i += 32) {
                int s = i >> 2, rr = i & 3;
                gout[(size_t)s * NST + rr] = osm[i];
            }
        }
    }

    float* sp = S_out + (size_t)b * (NST * NST) + (size_t)r * NST + c0;
    ((float4*)sp)[0] = make_float4(S[0], S[1], S[2], S[3]);
    ((float4*)sp)[1] = make_float4(S[4], S[5], S[6], S[7]);
}

// ---------------------------------------------------------------------------
// Launch
// ---------------------------------------------------------------------------
extern "C" void kernel_launch(void* const* d_in, const int* in_sizes, int n_in,
                              void* d_out, int out_size) {
    const float* x   = (const float*)d_in[0];
    const float* Win = (const float*)d_in[1];
    const float* Wk  = (const float*)d_in[2];
    const float* Wv  = (const float*)d_in[3];
    const float* Wq  = (const float*)d_in[4];
    const float* Wa  = (const float*)d_in[5];
    const float* dAl = (const float*)d_in[6];
    const float* bAl = (const float*)d_in[7];
    const float* Wout= (const float*)d_in[8];
    float* out = (float*)d_out;

    void *xhh_v, *xhl_v, *xph_v, *xpl_v, *wih_v, *wil_v, *wch_v, *wcl_v,
         *kvqa_v, *cell_v;
    cudaGetSymbolAddress(&xhh_v, g_xhh);  cudaGetSymbolAddress(&xhl_v, g_xhl);
    cudaGetSymbolAddress(&xph_v, g_xph);  cudaGetSymbolAddress(&xpl_v, g_xpl);
    cudaGetSymbolAddress(&wih_v, g_wih);  cudaGetSymbolAddress(&wil_v, g_wil);
    cudaGetSymbolAddress(&wch_v, g_wch);  cudaGetSymbolAddress(&wcl_v, g_wcl);
    cudaGetSymbolAddress(&kvqa_v, g_kvqa);
    cudaGetSymbolAddress(&cell_v, g_cell);
    __half* xhh = (__half*)xhh_v;  __half* xhl = (__half*)xhl_v;
    __half* xph = (__half*)xph_v;  __half* xpl = (__half*)xpl_v;
    __half* wih = (__half*)wih_v;  __half* wil = (__half*)wil_v;
    __half* wch = (__half*)wch_v;  __half* wcl = (__half*)wcl_v;
    float* kvqa = (float*)kvqa_v;
    float* cell = (float*)cell_v;

    cudaFuncSetAttribute(hgemm_kernel<0>,
                         cudaFuncAttributeMaxDynamicSharedMemorySize, SMEM_H);
    cudaFuncSetAttribute(hgemm_kernel<1>,
                         cudaFuncAttributeMaxDynamicSharedMemorySize, SMEM_H);

    // 0) conversions to fp16 hi/lo
    conv_hl_kernel<<<(MTOT * DIM / 8 + 255) / 256, 256>>>(x, xhh, xhl,
                                                          MTOT * DIM / 8);
    conv_hl_kernel<<<(DIM * DIM / 8 + 255) / 256, 256>>>(Win, wih, wil,
                                                         DIM * DIM / 8);
    conv_wcat_kernel<<<(256 * DIM / 8 + 255) / 256, 256>>>(Wk, Wv, Wq, Wa,
                                                           wch, wcl);

    // 1) xp = silu(x @ W_in^T)  (M=32768, N=1024, K=1024) -> fp16 hi/lo
    hgemm_kernel<1><<<dim3(DIM / BN, MTOT / BM), 256, SMEM_H>>>(
        xhh, xhl, wih, wil, nullptr, xph, xpl, DIM, DIM);

    // 2) kvqa = xp @ Wcat^T  (M=32768, N=256, K=1024) -> fp32
    hgemm_kernel<0><<<dim3(256 / BN, MTOT / BM), 256, SMEM_H>>>(
        xph, xpl, wch, wcl, kvqa, nullptr, nullptr, 256, DIM);

    // 3) fine row-split scan (also writes S_final to d_out tail)
    scan_kernel<<<BB * 16, 32>>>(kvqa, dAl, bAl, cell,
                                 out + (size_t)MTOT * DIM);

    // 4) output = cell @ W_out^T  (M=32768, N=1024, K=64)
    sgemm_kernel<<<dim3(DIM / 128, MTOT / 128), 256>>>(
        cell, Wout, out, MTOT, DIM, NST);
}

// round 16
// speedup vs baseline: 1.0343x; 1.0132x over previous
#include <cuda_runtime.h>
#include <cuda_fp16.h>
#include <cuda_bf16.h>
#include <cstdint>

// ---------------------------------------------------------------------------
// Problem constants
// ---------------------------------------------------------------------------
#define BB    16
#define TT    2048
#define DIM   1024
#define NST   64
#define MTOT  (BB * TT)          // 32768 rows

// HMMA GEMM tiling: CTA tile 256x128, warp tile 64x64 (8 warps, 4x2)
#define BM    256
#define BN    128
#define BK    16
#define LDSK  24                 // padded halves per smem row (48B)
#define AT_B  (256 * LDSK * 2)   // 12288 B  (Ah or Al tile)
#define BT_B  (128 * LDSK * 2)   // 6144 B   (Bh or Bl tile)
#define STG_B (2 * AT_B + 2 * BT_B)   // 36864 B per stage
#define SMEM_H (3 * STG_B)            // 110592 B (3 stages)

// ---------------------------------------------------------------------------
// Scratch (__device__ globals — no allocation allowed)
// ---------------------------------------------------------------------------
__device__ __align__(16) __half g_xhh[(size_t)MTOT * DIM];  // x hi
__device__ __align__(16) __half g_xhl[(size_t)MTOT * DIM];  // x lo
__device__ __align__(16) __half g_xph[(size_t)MTOT * DIM];  // xp hi
__device__ __align__(16) __half g_xpl[(size_t)MTOT * DIM];  // xp lo
__device__ __align__(16) __half g_wih[(size_t)DIM * DIM];   // W_in hi
__device__ __align__(16) __half g_wil[(size_t)DIM * DIM];   // W_in lo
__device__ __align__(16) __half g_wch[(size_t)256 * DIM];   // wcat hi
__device__ __align__(16) __half g_wcl[(size_t)256 * DIM];   // wcat lo
__device__ float g_kvqa[(size_t)MTOT * 256];   // 32 MB : [m][k|v|q|ax]
__device__ float g_cell[(size_t)MTOT * NST];   //  8 MB : gated cell output

// ---------------------------------------------------------------------------
// Helpers
// ---------------------------------------------------------------------------
__device__ __forceinline__ float fast_sigmoid(float x) {
    return __fdividef(1.0f, 1.0f + __expf(-x));
}

__device__ __forceinline__ uint32_t smem_u32(const void* p) {
    uint32_t a;
    asm("{ .reg .u64 t; cvta.to.shared.u64 t, %1; cvt.u32.u64 %0, t; }"
        : "=r"(a) : "l"(p));
    return a;
}

__device__ __forceinline__ void cp16(uint32_t dst, const void* src) {
    asm volatile("cp.async.cg.shared.global [%0], [%1], 16;"
                 :: "r"(dst), "l"(src));
}

__device__ __forceinline__ uint32_t lds32(uint32_t a) {
    uint32_t v;
    asm("ld.shared.b32 %0, [%1];" : "=r"(v) : "r"(a));
    return v;
}

__device__ __forceinline__ void mma16816(float* c, const uint32_t* a,
                                         const uint32_t* b) {
    asm volatile(
        "mma.sync.aligned.m16n8k16.row.col.f32.f16.f16.f32 "
        "{%0,%1,%2,%3}, {%4,%5,%6,%7}, {%8,%9}, {%0,%1,%2,%3};"
        : "+f"(c[0]), "+f"(c[1]), "+f"(c[2]), "+f"(c[3])
        : "r"(a[0]), "r"(a[1]), "r"(a[2]), "r"(a[3]), "r"(b[0]), "r"(b[1]));
}

__device__ __forceinline__ void ffma2(unsigned long long &acc,
                                      unsigned long long a,
                                      unsigned long long b) {
    asm("fma.rn.f32x2 %0, %1, %2, %0;" : "+l"(acc) : "l"(a), "l"(b));
}
__device__ __forceinline__ unsigned long long splat2(float v) {
    unsigned long long r;
    asm("mov.b64 %0, {%1, %1};" : "=l"(r) : "r"(__float_as_uint(v)));
    return r;
}

__device__ __forceinline__ void split_hl(float v, __half& h, __half& l) {
    h = __float2half_rn(v);
    l = __float2half_rn(v - __half2float(h));
}

// ---------------------------------------------------------------------------
// Conversion kernels: fp32 -> fp16 hi/lo, row-major, 8 elems per thread
// ---------------------------------------------------------------------------
__global__ void conv_hl_kernel(const float* __restrict__ src,
                               __half* __restrict__ hi,
                               __half* __restrict__ lo, int n8) {
    int t = blockIdx.x * blockDim.x + threadIdx.x;
    if (t >= n8) return;
    const float4* s = (const float4*)(src + (size_t)t * 8);
    float4 a = s[0], b = s[1];
    float v[8] = {a.x, a.y, a.z, a.w, b.x, b.y, b.z, b.w};
    __half hv[8], lv[8];
#pragma unroll
    for (int i = 0; i < 8; i++) split_hl(v[i], hv[i], lv[i]);
    *(uint4*)(hi + (size_t)t * 8) = *(uint4*)hv;
    *(uint4*)(lo + (size_t)t * 8) = *(uint4*)lv;
}

// wcat = concat(W_k,W_v,W_q,W_alpha)[256][1024] -> hi/lo
__global__ void conv_wcat_kernel(const float* __restrict__ Wk,
                                 const float* __restrict__ Wv,
                                 const float* __restrict__ Wq,
                                 const float* __restrict__ Wa,
                                 __half* __restrict__ hi,
                                 __half* __restrict__ lo) {
    int t = blockIdx.x * blockDim.x + threadIdx.x;   // 32768 threads
    if (t >= 256 * DIM / 8) return;
    int e0 = t * 8;
    int n = e0 >> 10;
    int j = e0 & 1023;
    const float* src = (n < 64) ? Wk : (n < 128) ? Wv : (n < 192) ? Wq : Wa;
    const float4* s = (const float4*)(src + (size_t)(n & 63) * DIM + j);
    float4 a = s[0], b = s[1];
    float v[8] = {a.x, a.y, a.z, a.w, b.x, b.y, b.z, b.w};
    __half hv[8], lv[8];
#pragma unroll
    for (int i = 0; i < 8; i++) split_hl(v[i], hv[i], lv[i]);
    *(uint4*)(hi + (size_t)e0) = *(uint4*)hv;
    *(uint4*)(lo + (size_t)e0) = *(uint4*)lv;
}

// ---------------------------------------------------------------------------
// HMMA GEMM (unchanged measured build): CTA 256x128, warp tile 64x64.
// fp16 hi/lo 3-term split, fp32 accum, 3-stage cp.async pipeline.
// EPI 0: fp32 C. EPI 1: silu -> fp16 hi/lo.
// ---------------------------------------------------------------------------
template <int EPI>
__global__ __launch_bounds__(256)
void hgemm_kernel(const __half* __restrict__ Ahg,
                  const __half* __restrict__ Alg,
                  const __half* __restrict__ Bhg,
                  const __half* __restrict__ Blg,
                  float* __restrict__ Cf,
                  __half* __restrict__ Oh,
                  __half* __restrict__ Ol,
                  int N, int K) {
    extern __shared__ __align__(16) __half hsm[];
    const int tid  = threadIdx.x;
    const int wid  = tid >> 5, lane = tid & 31;
    const int wm   = wid >> 1, wn = wid & 1;          // 4 x 2 warp grid
    const int gr   = lane >> 2, gc2 = (lane & 3) * 2;
    const int bm0  = blockIdx.y * BM;
    const int bn0  = blockIdx.x * BN;

    const __half* gAh = Ahg + (size_t)bm0 * K;
    const __half* gAl = Alg + (size_t)bm0 * K;
    const __half* gBh = Bhg + (size_t)bn0 * K;
    const __half* gBl = Blg + (size_t)bn0 * K;

    const uint32_t smu = smem_u32(hsm);

    float acc[4][8][4];
#pragma unroll
    for (int mi = 0; mi < 4; mi++)
#pragma unroll
        for (int ni = 0; ni < 8; ni++)
#pragma unroll
            for (int j = 0; j < 4; j++) acc[mi][ni][j] = 0.0f;

    const int NKT = K >> 4;

    // stage layout: [Ah 256r][Al 256r][Bh 128r][Bl 128r], 48 B/row,
    // 32 B loaded per row per k-tile -> 1536 cp16 = 6 per thread.
    auto load_stage = [&](int s, int kt) {
        uint32_t sb = smu + s * STG_B;
#pragma unroll
        for (int j = 0; j < 6; j++) {
            int c = tid + j * 256;          // 0..1535
            int rowcat = c >> 1, ch = c & 1;
            const __half* gp;
            if (rowcat < 256)      gp = gAh + (size_t)rowcat * K;
            else if (rowcat < 512) gp = gAl + (size_t)(rowcat - 256) * K;
            else if (rowcat < 640) gp = gBh + (size_t)(rowcat - 512) * K;
            else                   gp = gBl + (size_t)(rowcat - 640) * K;
            gp += kt * BK + ch * 8;
            cp16(sb + rowcat * (LDSK * 2) + ch * 16, gp);
        }
    };

    load_stage(0, 0);
    asm volatile("cp.async.commit_group;");
    load_stage(1, 1);
    asm volatile("cp.async.commit_group;");

    for (int kt = 0; kt < NKT; kt++) {
        asm volatile("cp.async.wait_group 1;");
        __syncthreads();

        if (kt + 2 < NKT) load_stage((kt + 2) % 3, kt + 2);
        asm volatile("cp.async.commit_group;");

        uint32_t sA  = smu + (kt % 3) * STG_B;       // Ah
        uint32_t sAl = sA + AT_B;
        uint32_t sBh = sA + 2 * AT_B;
        uint32_t sBl = sA + 2 * AT_B + BT_B;

        uint32_t a[4][4], bh[8][2];
        // keep all Bh fragments live (reused by Al*Bh)
#pragma unroll
        for (int ni = 0; ni < 8; ni++) {
            uint32_t off = ((wn * 64 + ni * 8 + gr) * LDSK + gc2) * 2;
            bh[ni][0] = lds32(sBh + off);
            bh[ni][1] = lds32(sBh + off + 16);
        }
        // a <- Ah
#pragma unroll
        for (int mi = 0; mi < 4; mi++) {
            uint32_t base = sA + ((wm * 64 + mi * 16 + gr) * LDSK + gc2) * 2;
            a[mi][0] = lds32(base);
            a[mi][1] = lds32(base + 8 * LDSK * 2);
            a[mi][2] = lds32(base + 16);
            a[mi][3] = lds32(base + 8 * LDSK * 2 + 16);
        }
        // Ah * Bh
#pragma unroll
        for (int mi = 0; mi < 4; mi++)
#pragma unroll
            for (int ni = 0; ni < 8; ni++)
                mma16816(acc[mi][ni], a[mi], bh[ni]);
        // Ah * Bl (transient bl fragments)
#pragma unroll
        for (int ni = 0; ni < 8; ni++) {
            uint32_t off = ((wn * 64 + ni * 8 + gr) * LDSK + gc2) * 2;
            uint32_t bl[2];
            bl[0] = lds32(sBl + off);
            bl[1] = lds32(sBl + off + 16);
#pragma unroll
            for (int mi = 0; mi < 4; mi++)
                mma16816(acc[mi][ni], a[mi], bl);
        }
        // a <- Al, then Al * Bh
#pragma unroll
        for (int mi = 0; mi < 4; mi++) {
            uint32_t base = sAl + ((wm * 64 + mi * 16 + gr) * LDSK + gc2) * 2;
            a[mi][0] = lds32(base);
            a[mi][1] = lds32(base + 8 * LDSK * 2);
            a[mi][2] = lds32(base + 16);
            a[mi][3] = lds32(base + 8 * LDSK * 2 + 16);
        }
#pragma unroll
        for (int mi = 0; mi < 4; mi++)
#pragma unroll
            for (int ni = 0; ni < 8; ni++)
                mma16816(acc[mi][ni], a[mi], bh[ni]);
    }

    // ---- epilogue ----
#pragma unroll
    for (int mi = 0; mi < 4; mi++) {
        int r0 = bm0 + wm * 64 + mi * 16 + gr;
#pragma unroll
        for (int ni = 0; ni < 8; ni++) {
            int col = bn0 + wn * 64 + ni * 8 + gc2;
            float* c = acc[mi][ni];
            if (EPI == 0) {
                *(float2*)&Cf[(size_t)r0 * N + col]       = make_float2(c[0], c[1]);
                *(float2*)&Cf[(size_t)(r0 + 8) * N + col] = make_float2(c[2], c[3]);
            } else {
                float s0 = c[0] * fast_sigmoid(c[0]);
                float s1 = c[1] * fast_sigmoid(c[1]);
                float s2 = c[2] * fast_sigmoid(c[2]);
                float s3 = c[3] * fast_sigmoid(c[3]);
                __half h0, l0, h1, l1, h2, l2, h3, l3;
                split_hl(s0, h0, l0); split_hl(s1, h1, l1);
                split_hl(s2, h2, l2); split_hl(s3, h3, l3);
                __half2 ph0; ph0.x = h0; ph0.y = h1;
                __half2 pl0; pl0.x = l0; pl0.y = l1;
                __half2 ph1; ph1.x = h2; ph1.y = h3;
                __half2 pl1; pl1.x = l2; pl1.y = l3;
                *(__half2*)&Oh[(size_t)r0 * N + col]       = ph0;
                *(__half2*)&Ol[(size_t)r0 * N + col]       = pl0;
                *(__half2*)&Oh[(size_t)(r0 + 8) * N + col] = ph1;
                *(__half2*)&Ol[(size_t)(r0 + 8) * N + col] = pl1;
            }
        }
    }
}

// ---------------------------------------------------------------------------
// GEMM3 (K=64): fp32 FFMA2 SGEMM  C[M,N] = A[M,K] * B[N,K]^T  (proven kernel)
// ---------------------------------------------------------------------------
__global__ __launch_bounds__(256, 2)
void sgemm_kernel(const float* __restrict__ A,
                  const float* __restrict__ B,
                  float* __restrict__ C,
                  int M, int N, int K) {
    __shared__ float As[2][8][128];
    __shared__ float Bs[2][8][128];

    const int tid = threadIdx.x;
    const int tx  = tid & 15;
    const int ty  = tid >> 4;
    const int bm0 = blockIdx.y * 128;
    const int bn0 = blockIdx.x * 128;
    const int lr = tid >> 1;
    const int lk = (tid & 1) * 4;

    const float* Aptr = A + (size_t)(bm0 + lr) * K + lk;
    const float* Bptr = B + (size_t)(bn0 + lr) * K + lk;

    unsigned long long acc[8][4];
#pragma unroll
    for (int i = 0; i < 8; i++)
#pragma unroll
        for (int j = 0; j < 4; j++) acc[i][j] = 0ULL;

    const int NIT = K >> 3;
    {
        float4 av = *(const float4*)Aptr;
        float4 bv = *(const float4*)Bptr;
        As[0][lk + 0][lr] = av.x; As[0][lk + 1][lr] = av.y;
        As[0][lk + 2][lr] = av.z; As[0][lk + 3][lr] = av.w;
        Bs[0][lk + 0][lr] = bv.x; Bs[0][lk + 1][lr] = bv.y;
        Bs[0][lk + 2][lr] = bv.z; Bs[0][lk + 3][lr] = bv.w;
    }
    __syncthreads();

    int buf = 0;
    for (int it = 0; it < NIT; ++it) {
        float4 an, bn_;
        const bool pf = (it + 1 < NIT);
        if (pf) {
            an  = *(const float4*)(Aptr + (size_t)(it + 1) * 8);
            bn_ = *(const float4*)(Bptr + (size_t)(it + 1) * 8);
        }
#pragma unroll
        for (int k = 0; k < 8; k++) {
            float4 a0 = *(const float4*)&As[buf][k][ty * 4];
            float4 a1 = *(const float4*)&As[buf][k][ty * 4 + 64];
            float4 b0 = *(const float4*)&Bs[buf][k][tx * 4];
            float4 b1 = *(const float4*)&Bs[buf][k][tx * 4 + 64];
            unsigned long long bp[4];
            bp[0] = ((const unsigned long long*)&b0)[0];
            bp[1] = ((const unsigned long long*)&b0)[1];
            bp[2] = ((const unsigned long long*)&b1)[0];
            bp[3] = ((const unsigned long long*)&b1)[1];
            float ar[8] = {a0.x, a0.y, a0.z, a0.w, a1.x, a1.y, a1.z, a1.w};
#pragma unroll
            for (int i = 0; i < 8; i++) {
                unsigned long long ap = splat2(ar[i]);
#pragma unroll
                for (int j = 0; j < 4; j++) ffma2(acc[i][j], ap, bp[j]);
            }
        }
        if (pf) {
            int nb2 = buf ^ 1;
            As[nb2][lk + 0][lr] = an.x;  As[nb2][lk + 1][lr] = an.y;
            As[nb2][lk + 2][lr] = an.z;  As[nb2][lk + 3][lr] = an.w;
            Bs[nb2][lk + 0][lr] = bn_.x; Bs[nb2][lk + 1][lr] = bn_.y;
            Bs[nb2][lk + 2][lr] = bn_.z; Bs[nb2][lk + 3][lr] = bn_.w;
        }
        __syncthreads();
        buf ^= 1;
    }

#pragma unroll
    for (int i = 0; i < 8; i++) {
        int rloc = (i < 4) ? (ty * 4 + i) : (64 + ty * 4 + (i - 4));
        int m = bm0 + rloc;
        float v[8];
#pragma unroll
        for (int j = 0; j < 4; j++) {
            v[2 * j]     = __uint_as_float((unsigned)(acc[i][j]));
            v[2 * j + 1] = __uint_as_float((unsigned)(acc[i][j] >> 32));
        }
        float* cp = C + (size_t)m * N + bn0;
        *(float4*)(cp + tx * 4)      = make_float4(v[0], v[1], v[2], v[3]);
        *(float4*)(cp + 64 + tx * 4) = make_float4(v[4], v[5], v[6], v[7]);
    }
}

// ---------------------------------------------------------------------------
// Sequential gated scan, WARP-SPECIALIZED: 128 CTAs x 128 threads.
// CTA = (batch, 8-row block). Warp 0 = compute (SMSP 0): 8 rows x 4 lanes,
// 16 S-columns per lane (proven R8 layout). Warps 1-3 = loaders (SMSPs
// 1-3): 576 cp16 per chunk (full k,q + own-8-row v,ax), 6 per lane.
// Rationale: cp.async issue rate (8 cyc/op/SMSP) was the scan limiter when
// one warp both loaded (1024 cp16/chunk) and computed.
// ---------------------------------------------------------------------------
#define SCH 16

__global__ __launch_bounds__(128, 1)
void scan_kernel(const float* __restrict__ kvqa,
                 const float* __restrict__ d_alpha,
                 const float* __restrict__ b_alpha,
                 float* __restrict__ cell,
                 float* __restrict__ S_out) {
    __shared__ float buf[2][SCH * 256];

    const int b    = blockIdx.x >> 3;
    const int rb   = blockIdx.x & 7;
    const int tid  = threadIdx.x;
    const int wid  = tid >> 5;
    const int lane = tid & 31;

    const char* gsrcb = (const char*)(kvqa + (size_t)b * TT * 256);
    const int NCH = TT / SCH;   // 128

    if (wid > 0) {
        // ---------------- loader warps (1..3) ----------------
        const int lt = tid - 32;             // 0..95
        // per-chunk offset table: 36 cp16 per step (16 k, 16 q, 2 v, 2 ax)
        uint32_t offs[6];
#pragma unroll
        for (int j = 0; j < 6; j++) {
            int i = lt + j * 96;             // 0..575
            int s = i / 36;
            int w = i - s * 36;
            uint32_t off;
            if (w < 16)      off = (uint32_t)(s * 1024 + w * 16);
            else if (w < 32) off = (uint32_t)(s * 1024 + 512 + (w - 16) * 16);
            else if (w < 34) off = (uint32_t)(s * 1024 + 256 + rb * 32 + (w - 32) * 16);
            else             off = (uint32_t)(s * 1024 + 768 + rb * 32 + (w - 34) * 16);
            offs[j] = off;
        }
        uint32_t sb0 = (uint32_t)__cvta_generic_to_shared(&buf[0][0]);
        uint32_t sb1 = (uint32_t)__cvta_generic_to_shared(&buf[1][0]);

        // prologue: chunk 0
#pragma unroll
        for (int j = 0; j < 6; j++)
            cp16(sb0 + offs[j], gsrcb + offs[j]);
        asm volatile("cp.async.commit_group;");

        for (int c = 0; c < NCH; ++c) {
            if (c + 1 < NCH) {
                uint32_t sb = ((c + 1) & 1) ? sb1 : sb0;
                const char* g = gsrcb + (size_t)(c + 1) * (SCH * 1024);
#pragma unroll
                for (int j = 0; j < 6; j++)
                    cp16(sb + offs[j], g + offs[j]);
                asm volatile("cp.async.commit_group;");
                asm volatile("cp.async.wait_group 1;");
            } else {
                asm volatile("cp.async.wait_group 0;");
            }
            __syncthreads();   // publish chunk c
            __syncthreads();   // compute done with buf[c&1]
        }
    } else {
        // ---------------- compute warp (0) ----------------
        const int rloc = lane >> 2;         // 0..7
        const int r    = rb * 8 + rloc;     // global state row
        const int h    = lane & 3;
        const int c0   = h * 16;

        float S[16];
#pragma unroll
        for (int j = 0; j < 16; j++) S[j] = 0.0f;

        const float dA = d_alpha[r];
        const float bA = b_alpha[r];

        for (int c = 0; c < NCH; ++c) {
            __syncthreads();   // chunk c ready
            const float* cb = &buf[c & 1][0];
            float* gout = cell + ((size_t)b * TT + (size_t)c * SCH) * NST
                        + rb * 8 + rloc;
#pragma unroll 2
            for (int s = 0; s < SCH; ++s) {
                const float* p = cb + s * 256;

                float4 k4[4];
                const float4* kp = (const float4*)(p + c0);
#pragma unroll
                for (int i = 0; i < 4; i++) k4[i] = kp[i];

                float r0 = 0.f, r1 = 0.f, r2 = 0.f, r3 = 0.f;
#pragma unroll
                for (int i = 0; i < 4; i++) {
                    r0 = fmaf(S[4 * i + 0], k4[i].x, r0);
                    r1 = fmaf(S[4 * i + 1], k4[i].y, r1);
                    r2 = fmaf(S[4 * i + 2], k4[i].z, r2);
                    r3 = fmaf(S[4 * i + 3], k4[i].w, r3);
                }
                float rp = (r0 + r1) + (r2 + r3);
                rp += __shfl_xor_sync(0xffffffffu, rp, 1);
                rp += __shfl_xor_sync(0xffffffffu, rp, 2);

                float axv = p[192 + r];
                float vv  = p[64 + r];
                float araw = fmaf(dA, rp, axv + bA);
                float al   = fast_sigmoid(araw);
                float cc   = (1.0f - al) * vv;

                float o0 = 0.f, o1 = 0.f, o2 = 0.f, o3 = 0.f;
                const float4* qp = (const float4*)(p + 128 + c0);
#pragma unroll
                for (int i = 0; i < 4; i++) {
                    float4 q4 = qp[i];
                    S[4 * i + 0] = fmaf(al, S[4 * i + 0], cc * k4[i].x);
                    S[4 * i + 1] = fmaf(al, S[4 * i + 1], cc * k4[i].y);
                    S[4 * i + 2] = fmaf(al, S[4 * i + 2], cc * k4[i].z);
                    S[4 * i + 3] = fmaf(al, S[4 * i + 3], cc * k4[i].w);
                    o0 = fmaf(S[4 * i + 0], q4.x, o0);
                    o1 = fmaf(S[4 * i + 1], q4.y, o1);
                    o2 = fmaf(S[4 * i + 2], q4.z, o2);
                    o3 = fmaf(S[4 * i + 3], q4.w, o3);
                }
                float o = (o0 + o1) + (o2 + o3);
                o += __shfl_xor_sync(0xffffffffu, o, 1);
                o += __shfl_xor_sync(0xffffffffu, o, 2);

                if (h == 0) {
                    float sg = fast_sigmoid(o);
                    gout[(size_t)s * NST] = o * o * sg;   // o * silu(o)
                }
            }
            __syncthreads();   // release buf[c&1] for refill
        }

        float* sp = S_out + (size_t)b * (NST * NST) + (size_t)r * NST + c0;
#pragma unroll
        for (int i = 0; i < 4; i++)
            ((float4*)sp)[i] = make_float4(S[4 * i + 0], S[4 * i + 1],
                                           S[4 * i + 2], S[4 * i + 3]);
    }
}

// ---------------------------------------------------------------------------
// Launch
// ---------------------------------------------------------------------------
extern "C" void kernel_launch(void* const* d_in, const int* in_sizes, int n_in,
                              void* d_out, int out_size) {
    const float* x   = (const float*)d_in[0];
    const float* Win = (const float*)d_in[1];
    const float* Wk  = (const float*)d_in[2];
    const float* Wv  = (const float*)d_in[3];
    const float* Wq  = (const float*)d_in[4];
    const float* Wa  = (const float*)d_in[5];
    const float* dAl = (const float*)d_in[6];
    const float* bAl = (const float*)d_in[7];
    const float* Wout= (const float*)d_in[8];
    float* out = (float*)d_out;

    void *xhh_v, *xhl_v, *xph_v, *xpl_v, *wih_v, *wil_v, *wch_v, *wcl_v,
         *kvqa_v, *cell_v;
    cudaGetSymbolAddress(&xhh_v, g_xhh);  cudaGetSymbolAddress(&xhl_v, g_xhl);
    cudaGetSymbolAddress(&xph_v, g_xph);  cudaGetSymbolAddress(&xpl_v, g_xpl);
    cudaGetSymbolAddress(&wih_v, g_wih);  cudaGetSymbolAddress(&wil_v, g_wil);
    cudaGetSymbolAddress(&wch_v, g_wch);  cudaGetSymbolAddress(&wcl_v, g_wcl);
    cudaGetSymbolAddress(&kvqa_v, g_kvqa);
    cudaGetSymbolAddress(&cell_v, g_cell);
    __half* xhh = (__half*)xhh_v;  __half* xhl = (__half*)xhl_v;
    __half* xph = (__half*)xph_v;  __half* xpl = (__half*)xpl_v;
    __half* wih = (__half*)wih_v;  __half* wil = (__half*)wil_v;
    __half* wch = (__half*)wch_v;  __half* wcl = (__half*)wcl_v;
    float* kvqa = (float*)kvqa_v;
    float* cell = (float*)cell_v;

    cudaFuncSetAttribute(hgemm_kernel<0>,
                         cudaFuncAttributeMaxDynamicSharedMemorySize, SMEM_H);
    cudaFuncSetAttribute(hgemm_kernel<1>,
                         cudaFuncAttributeMaxDynamicSharedMemorySize, SMEM_H);

    // 0) conversions to fp16 hi/lo
    conv_hl_kernel<<<(MTOT * DIM / 8 + 255) / 256, 256>>>(x, xhh, xhl,
                                                          MTOT * DIM / 8);
    conv_hl_kernel<<<(DIM * DIM / 8 + 255) / 256, 256>>>(Win, wih, wil,
                                                         DIM * DIM / 8);
    conv_wcat_kernel<<<(256 * DIM / 8 + 255) / 256, 256>>>(Wk, Wv, Wq, Wa,
                                                           wch, wcl);

    // 1) xp = silu(x @ W_in^T)  (M=32768, N=1024, K=1024) -> fp16 hi/lo
    hgemm_kernel<1><<<dim3(DIM / BN, MTOT / BM), 256, SMEM_H>>>(
        xhh, xhl, wih, wil, nullptr, xph, xpl, DIM, DIM);

    // 2) kvqa = xp @ Wcat^T  (M=32768, N=256, K=1024) -> fp32
    hgemm_kernel<0><<<dim3(256 / BN, MTOT / BM), 256, SMEM_H>>>(
        xph, xpl, wch, wcl, kvqa, nullptr, nullptr, 256, DIM);

    // 3) warp-specialized row-split scan (also writes S_final to d_out tail)
    scan_kernel<<<BB * 8, 128>>>(kvqa, dAl, bAl, cell,
                                 out + (size_t)MTOT * DIM);

    // 4) output = cell @ W_out^T  (M=32768, N=1024, K=64)
    sgemm_kernel<<<dim3(DIM / 128, MTOT / 128), 256>>>(
        cell, Wout, out, MTOT, DIM, NST);
}

// round 17
// speedup vs baseline: 1.1488x; 1.1107x over previous
#include <cuda_runtime.h>
#include <cuda_fp16.h>
#include <cuda_bf16.h>
#include <cstdint>

// ---------------------------------------------------------------------------
// Problem constants
// ---------------------------------------------------------------------------
#define BB    16
#define TT    2048
#define DIM   1024
#define NST   64
#define MTOT  (BB * TT)          // 32768 rows

// HMMA GEMM tiling: CTA tile 256x128, warp tile 64x64 (8 warps, 4x2)
// 2-term split: A = Ah + Al (fp16 hi/lo), B single fp16.
#define BM    256
#define BN    128
#define BK    16
#define LDSK  24                 // padded halves per smem row (48B)
#define AT_B  (256 * LDSK * 2)   // 12288 B  (Ah or Al tile)
#define BT_B  (128 * LDSK * 2)   // 6144 B   (B tile)
#define STG_B (2 * AT_B + BT_B)  // 30720 B per stage (Ah,Al,B)
#define SMEM_H (3 * STG_B)       // 92160 B (3 stages)

// ---------------------------------------------------------------------------
// Scratch (__device__ globals — no allocation allowed)
// ---------------------------------------------------------------------------
__device__ __align__(16) __half g_xhh[(size_t)MTOT * DIM];  // x hi
__device__ __align__(16) __half g_xhl[(size_t)MTOT * DIM];  // x lo
__device__ __align__(16) __half g_xph[(size_t)MTOT * DIM];  // xp hi
__device__ __align__(16) __half g_xpl[(size_t)MTOT * DIM];  // xp lo
__device__ __align__(16) __half g_wih[(size_t)DIM * DIM];   // W_in fp16
__device__ __align__(16) __half g_wch[(size_t)256 * DIM];   // wcat fp16
__device__ float g_kvqa[(size_t)MTOT * 256];   // 32 MB : [m][k|v|q|ax]
__device__ float g_cell[(size_t)MTOT * NST];   //  8 MB : gated cell output
__device__ float g_oscr[1024];                 // dummy sink for first deferred o

// ---------------------------------------------------------------------------
// Helpers
// ---------------------------------------------------------------------------
__device__ __forceinline__ float fast_sigmoid(float x) {
    return __fdividef(1.0f, 1.0f + __expf(-x));
}

__device__ __forceinline__ uint32_t smem_u32(const void* p) {
    uint32_t a;
    asm("{ .reg .u64 t; cvta.to.shared.u64 t, %1; cvt.u32.u64 %0, t; }"
        : "=r"(a) : "l"(p));
    return a;
}

__device__ __forceinline__ void cp16(uint32_t dst, const void* src) {
    asm volatile("cp.async.cg.shared.global [%0], [%1], 16;"
                 :: "r"(dst), "l"(src));
}

__device__ __forceinline__ uint32_t lds32(uint32_t a) {
    uint32_t v;
    asm("ld.shared.b32 %0, [%1];" : "=r"(v) : "r"(a));
    return v;
}

__device__ __forceinline__ void mma16816(float* c, const uint32_t* a,
                                         const uint32_t* b) {
    asm volatile(
        "mma.sync.aligned.m16n8k16.row.col.f32.f16.f16.f32 "
        "{%0,%1,%2,%3}, {%4,%5,%6,%7}, {%8,%9}, {%0,%1,%2,%3};"
        : "+f"(c[0]), "+f"(c[1]), "+f"(c[2]), "+f"(c[3])
        : "r"(a[0]), "r"(a[1]), "r"(a[2]), "r"(a[3]), "r"(b[0]), "r"(b[1]));
}

__device__ __forceinline__ void ffma2(unsigned long long &acc,
                                      unsigned long long a,
                                      unsigned long long b) {
    asm("fma.rn.f32x2 %0, %1, %2, %0;" : "+l"(acc) : "l"(a), "l"(b));
}
__device__ __forceinline__ unsigned long long splat2(float v) {
    unsigned long long r;
    asm("mov.b64 %0, {%1, %1};" : "=l"(r) : "r"(__float_as_uint(v)));
    return r;
}

__device__ __forceinline__ void split_hl(float v, __half& h, __half& l) {
    h = __float2half_rn(v);
    l = __float2half_rn(v - __half2float(h));
}

// ---------------------------------------------------------------------------
// Conversion kernels
// ---------------------------------------------------------------------------
__global__ void conv_hl_kernel(const float* __restrict__ src,
                               __half* __restrict__ hi,
                               __half* __restrict__ lo, int n8) {
    int t = blockIdx.x * blockDim.x + threadIdx.x;
    if (t >= n8) return;
    const float4* s = (const float4*)(src + (size_t)t * 8);
    float4 a = s[0], b = s[1];
    float v[8] = {a.x, a.y, a.z, a.w, b.x, b.y, b.z, b.w};
    __half hv[8], lv[8];
#pragma unroll
    for (int i = 0; i < 8; i++) split_hl(v[i], hv[i], lv[i]);
    *(uint4*)(hi + (size_t)t * 8) = *(uint4*)hv;
    *(uint4*)(lo + (size_t)t * 8) = *(uint4*)lv;
}

// fp32 -> single fp16 (round-to-nearest)
__global__ void conv_h_kernel(const float* __restrict__ src,
                              __half* __restrict__ hi, int n8) {
    int t = blockIdx.x * blockDim.x + threadIdx.x;
    if (t >= n8) return;
    const float4* s = (const float4*)(src + (size_t)t * 8);
    float4 a = s[0], b = s[1];
    float v[8] = {a.x, a.y, a.z, a.w, b.x, b.y, b.z, b.w};
    __half hv[8];
#pragma unroll
    for (int i = 0; i < 8; i++) hv[i] = __float2half_rn(v[i]);
    *(uint4*)(hi + (size_t)t * 8) = *(uint4*)hv;
}

// wcat = concat(W_k,W_v,W_q,W_alpha)[256][1024] -> single fp16
__global__ void conv_wcat_kernel(const float* __restrict__ Wk,
                                 const float* __restrict__ Wv,
                                 const float* __restrict__ Wq,
                                 const float* __restrict__ Wa,
                                 __half* __restrict__ hi) {
    int t = blockIdx.x * blockDim.x + threadIdx.x;   // 32768 threads
    if (t >= 256 * DIM / 8) return;
    int e0 = t * 8;
    int n = e0 >> 10;
    int j = e0 & 1023;
    const float* src = (n < 64) ? Wk : (n < 128) ? Wv : (n < 192) ? Wq : Wa;
    const float4* s = (const float4*)(src + (size_t)(n & 63) * DIM + j);
    float4 a = s[0], b = s[1];
    float v[8] = {a.x, a.y, a.z, a.w, b.x, b.y, b.z, b.w};
    __half hv[8];
#pragma unroll
    for (int i = 0; i < 8; i++) hv[i] = __float2half_rn(v[i]);
    *(uint4*)(hi + (size_t)e0) = *(uint4*)hv;
}

// ---------------------------------------------------------------------------
// HMMA GEMM, 2-TERM: C = (Ah + Al) * B^T, fp32 accum.
// CTA 256x128, 8 warps (4x2), warp tile 64x64. Per warp-k-tile: 64 MMA,
// 48 LDS (was 96 MMA / 64 LDS in 3-term). Stage = Ah,Al,B (30 KB).
// EPI 0: fp32 C. EPI 1: silu -> fp16 hi/lo.
// ---------------------------------------------------------------------------
template <int EPI>
__global__ __launch_bounds__(256)
void hgemm_kernel(const __half* __restrict__ Ahg,
                  const __half* __restrict__ Alg,
                  const __half* __restrict__ Bg,
                  float* __restrict__ Cf,
                  __half* __restrict__ Oh,
                  __half* __restrict__ Ol,
                  int N, int K) {
    extern __shared__ __align__(16) __half hsm[];
    const int tid  = threadIdx.x;
    const int wid  = tid >> 5, lane = tid & 31;
    const int wm   = wid >> 1, wn = wid & 1;          // 4 x 2 warp grid
    const int gr   = lane >> 2, gc2 = (lane & 3) * 2;
    const int bm0  = blockIdx.y * BM;
    const int bn0  = blockIdx.x * BN;

    const __half* gAh = Ahg + (size_t)bm0 * K;
    const __half* gAl = Alg + (size_t)bm0 * K;
    const __half* gB  = Bg  + (size_t)bn0 * K;

    const uint32_t smu = smem_u32(hsm);

    float acc[4][8][4];
#pragma unroll
    for (int mi = 0; mi < 4; mi++)
#pragma unroll
        for (int ni = 0; ni < 8; ni++)
#pragma unroll
            for (int j = 0; j < 4; j++) acc[mi][ni][j] = 0.0f;

    const int NKT = K >> 4;

    // stage layout: [Ah 256r][Al 256r][B 128r], 48 B/row, 32 B per row per
    // k-tile -> 1280 cp16 = 5 per thread.
    auto load_stage = [&](int s, int kt) {
        uint32_t sb = smu + s * STG_B;
#pragma unroll
        for (int j = 0; j < 5; j++) {
            int c = tid + j * 256;          // 0..1279
            int rowcat = c >> 1, ch = c & 1;
            const __half* gp;
            if (rowcat < 256)      gp = gAh + (size_t)rowcat * K;
            else if (rowcat < 512) gp = gAl + (size_t)(rowcat - 256) * K;
            else                   gp = gB  + (size_t)(rowcat - 512) * K;
            gp += kt * BK + ch * 8;
            cp16(sb + rowcat * (LDSK * 2) + ch * 16, gp);
        }
    };

    load_stage(0, 0);
    asm volatile("cp.async.commit_group;");
    load_stage(1, 1);
    asm volatile("cp.async.commit_group;");

    for (int kt = 0; kt < NKT; kt++) {
        asm volatile("cp.async.wait_group 1;");
        __syncthreads();

        if (kt + 2 < NKT) load_stage((kt + 2) % 3, kt + 2);
        asm volatile("cp.async.commit_group;");

        uint32_t sA  = smu + (kt % 3) * STG_B;       // Ah
        uint32_t sAl = sA + AT_B;
        uint32_t sB  = sA + 2 * AT_B;

        uint32_t a[4][4], bh[8][2];
#pragma unroll
        for (int ni = 0; ni < 8; ni++) {
            uint32_t off = ((wn * 64 + ni * 8 + gr) * LDSK + gc2) * 2;
            bh[ni][0] = lds32(sB + off);
            bh[ni][1] = lds32(sB + off + 16);
        }
        // a <- Ah ; Ah * B
#pragma unroll
        for (int mi = 0; mi < 4; mi++) {
            uint32_t base = sA + ((wm * 64 + mi * 16 + gr) * LDSK + gc2) * 2;
            a[mi][0] = lds32(base);
            a[mi][1] = lds32(base + 8 * LDSK * 2);
            a[mi][2] = lds32(base + 16);
            a[mi][3] = lds32(base + 8 * LDSK * 2 + 16);
        }
#pragma unroll
        for (int mi = 0; mi < 4; mi++)
#pragma unroll
            for (int ni = 0; ni < 8; ni++)
                mma16816(acc[mi][ni], a[mi], bh[ni]);
        // a <- Al ; Al * B
#pragma unroll
        for (int mi = 0; mi < 4; mi++) {
            uint32_t base = sAl + ((wm * 64 + mi * 16 + gr) * LDSK + gc2) * 2;
            a[mi][0] = lds32(base);
            a[mi][1] = lds32(base + 8 * LDSK * 2);
            a[mi][2] = lds32(base + 16);
            a[mi][3] = lds32(base + 8 * LDSK * 2 + 16);
        }
#pragma unroll
        for (int mi = 0; mi < 4; mi++)
#pragma unroll
            for (int ni = 0; ni < 8; ni++)
                mma16816(acc[mi][ni], a[mi], bh[ni]);
    }

    // ---- epilogue ----
#pragma unroll
    for (int mi = 0; mi < 4; mi++) {
        int r0 = bm0 + wm * 64 + mi * 16 + gr;
#pragma unroll
        for (int ni = 0; ni < 8; ni++) {
            int col = bn0 + wn * 64 + ni * 8 + gc2;
            float* c = acc[mi][ni];
            if (EPI == 0) {
                *(float2*)&Cf[(size_t)r0 * N + col]       = make_float2(c[0], c[1]);
                *(float2*)&Cf[(size_t)(r0 + 8) * N + col] = make_float2(c[2], c[3]);
            } else {
                float s0 = c[0] * fast_sigmoid(c[0]);
                float s1 = c[1] * fast_sigmoid(c[1]);
                float s2 = c[2] * fast_sigmoid(c[2]);
                float s3 = c[3] * fast_sigmoid(c[3]);
                __half h0, l0, h1, l1, h2, l2, h3, l3;
                split_hl(s0, h0, l0); split_hl(s1, h1, l1);
                split_hl(s2, h2, l2); split_hl(s3, h3, l3);
                __half2 ph0; ph0.x = h0; ph0.y = h1;
                __half2 pl0; pl0.x = l0; pl0.y = l1;
                __half2 ph1; ph1.x = h2; ph1.y = h3;
                __half2 pl1; pl1.x = l2; pl1.y = l3;
                *(__half2*)&Oh[(size_t)r0 * N + col]       = ph0;
                *(__half2*)&Ol[(size_t)r0 * N + col]       = pl0;
                *(__half2*)&Oh[(size_t)(r0 + 8) * N + col] = ph1;
                *(__half2*)&Ol[(size_t)(r0 + 8) * N + col] = pl1;
            }
        }
    }
}

// ---------------------------------------------------------------------------
// GEMM3 (K=64): fp32 FFMA2 SGEMM  C[M,N] = A[M,K] * B[N,K]^T  (proven kernel)
// ---------------------------------------------------------------------------
__global__ __launch_bounds__(256, 2)
void sgemm_kernel(const float* __restrict__ A,
                  const float* __restrict__ B,
                  float* __restrict__ C,
                  int M, int N, int K) {
    __shared__ float As[2][8][128];
    __shared__ float Bs[2][8][128];

    const int tid = threadIdx.x;
    const int tx  = tid & 15;
    const int ty  = tid >> 4;
    const int bm0 = blockIdx.y * 128;
    const int bn0 = blockIdx.x * 128;
    const int lr = tid >> 1;
    const int lk = (tid & 1) * 4;

    const float* Aptr = A + (size_t)(bm0 + lr) * K + lk;
    const float* Bptr = B + (size_t)(bn0 + lr) * K + lk;

    unsigned long long acc[8][4];
#pragma unroll
    for (int i = 0; i < 8; i++)
#pragma unroll
        for (int j = 0; j < 4; j++) acc[i][j] = 0ULL;

    const int NIT = K >> 3;
    {
        float4 av = *(const float4*)Aptr;
        float4 bv = *(const float4*)Bptr;
        As[0][lk + 0][lr] = av.x; As[0][lk + 1][lr] = av.y;
        As[0][lk + 2][lr] = av.z; As[0][lk + 3][lr] = av.w;
        Bs[0][lk + 0][lr] = bv.x; Bs[0][lk + 1][lr] = bv.y;
        Bs[0][lk + 2][lr] = bv.z; Bs[0][lk + 3][lr] = bv.w;
    }
    __syncthreads();

    int buf = 0;
    for (int it = 0; it < NIT; ++it) {
        float4 an, bn_;
        const bool pf = (it + 1 < NIT);
        if (pf) {
            an  = *(const float4*)(Aptr + (size_t)(it + 1) * 8);
            bn_ = *(const float4*)(Bptr + (size_t)(it + 1) * 8);
        }
#pragma unroll
        for (int k = 0; k < 8; k++) {
            float4 a0 = *(const float4*)&As[buf][k][ty * 4];
            float4 a1 = *(const float4*)&As[buf][k][ty * 4 + 64];
            float4 b0 = *(const float4*)&Bs[buf][k][tx * 4];
            float4 b1 = *(const float4*)&Bs[buf][k][tx * 4 + 64];
            unsigned long long bp[4];
            bp[0] = ((const unsigned long long*)&b0)[0];
            bp[1] = ((const unsigned long long*)&b0)[1];
            bp[2] = ((const unsigned long long*)&b1)[0];
            bp[3] = ((const unsigned long long*)&b1)[1];
            float ar[8] = {a0.x, a0.y, a0.z, a0.w, a1.x, a1.y, a1.z, a1.w};
#pragma unroll
            for (int i = 0; i < 8; i++) {
                unsigned long long ap = splat2(ar[i]);
#pragma unroll
                for (int j = 0; j < 4; j++) ffma2(acc[i][j], ap, bp[j]);
            }
        }
        if (pf) {
            int nb2 = buf ^ 1;
            As[nb2][lk + 0][lr] = an.x;  As[nb2][lk + 1][lr] = an.y;
            As[nb2][lk + 2][lr] = an.z;  As[nb2][lk + 3][lr] = an.w;
            Bs[nb2][lk + 0][lr] = bn_.x; Bs[nb2][lk + 1][lr] = bn_.y;
            Bs[nb2][lk + 2][lr] = bn_.z; Bs[nb2][lk + 3][lr] = bn_.w;
        }
        __syncthreads();
        buf ^= 1;
    }

#pragma unroll
    for (int i = 0; i < 8; i++) {
        int rloc = (i < 4) ? (ty * 4 + i) : (64 + ty * 4 + (i - 4));
        int m = bm0 + rloc;
        float v[8];
#pragma unroll
        for (int j = 0; j < 4; j++) {
            v[2 * j]     = __uint_as_float((unsigned)(acc[i][j]));
            v[2 * j + 1] = __uint_as_float((unsigned)(acc[i][j] >> 32));
        }
        float* cp = C + (size_t)m * N + bn0;
        *(float4*)(cp + tx * 4)      = make_float4(v[0], v[1], v[2], v[3]);
        *(float4*)(cp + 64 + tx * 4) = make_float4(v[4], v[5], v[6], v[7]);
    }
}

// ---------------------------------------------------------------------------
// Sequential gated scan, WARP-SPECIALIZED + DEFERRED-O.
// 128 CTAs x 128 threads. Warp 0 computes (8 rows x 4 lanes, 16 cols/lane);
// warps 1-3 load (576 cp16/chunk: full k,q + own 8 rows of v,ax).
// The o-reduction (2 SHFL + sigmoid + STG) of step s is issued at the top of
// step s+1, overlapping the k/q LDS latency instead of stalling the in-order
// warp at the end of each step. Arithmetic identical to R16.
// ---------------------------------------------------------------------------
#define SCH 16

__global__ __launch_bounds__(128, 1)
void scan_kernel(const float* __restrict__ kvqa,
                 const float* __restrict__ d_alpha,
                 const float* __restrict__ b_alpha,
                 float* __restrict__ cell,
                 float* __restrict__ S_out) {
    __shared__ float buf[2][SCH * 256];

    const int b    = blockIdx.x >> 3;
    const int rb   = blockIdx.x & 7;
    const int tid  = threadIdx.x;
    const int wid  = tid >> 5;
    const int lane = tid & 31;

    const char* gsrcb = (const char*)(kvqa + (size_t)b * TT * 256);
    const int NCH = TT / SCH;   // 128

    if (wid > 0) {
        // ---------------- loader warps (1..3) ----------------
        const int lt = tid - 32;             // 0..95
        uint32_t offs[6];
#pragma unroll
        for (int j = 0; j < 6; j++) {
            int i = lt + j * 96;             // 0..575
            int s = i / 36;
            int w = i - s * 36;
            uint32_t off;
            if (w < 16)      off = (uint32_t)(s * 1024 + w * 16);
            else if (w < 32) off = (uint32_t)(s * 1024 + 512 + (w - 16) * 16);
            else if (w < 34) off = (uint32_t)(s * 1024 + 256 + rb * 32 + (w - 32) * 16);
            else             off = (uint32_t)(s * 1024 + 768 + rb * 32 + (w - 34) * 16);
            offs[j] = off;
        }
        uint32_t sb0 = (uint32_t)__cvta_generic_to_shared(&buf[0][0]);
        uint32_t sb1 = (uint32_t)__cvta_generic_to_shared(&buf[1][0]);

#pragma unroll
        for (int j = 0; j < 6; j++)
            cp16(sb0 + offs[j], gsrcb + offs[j]);
        asm volatile("cp.async.commit_group;");

        for (int c = 0; c < NCH; ++c) {
            if (c + 1 < NCH) {
                uint32_t sb = ((c + 1) & 1) ? sb1 : sb0;
                const char* g = gsrcb + (size_t)(c + 1) * (SCH * 1024);
#pragma unroll
                for (int j = 0; j < 6; j++)
                    cp16(sb + offs[j], g + offs[j]);
                asm volatile("cp.async.commit_group;");
                asm volatile("cp.async.wait_group 1;");
            } else {
                asm volatile("cp.async.wait_group 0;");
            }
            __syncthreads();   // publish chunk c
            __syncthreads();   // compute done with buf[c&1]
        }
    } else {
        // ---------------- compute warp (0) ----------------
        const int rloc = lane >> 2;         // 0..7
        const int r    = rb * 8 + rloc;     // global state row
        const int h    = lane & 3;
        const int c0   = h * 16;

        float S[16];
#pragma unroll
        for (int j = 0; j < 16; j++) S[j] = 0.0f;

        const float dA = d_alpha[r];
        const float bA = b_alpha[r];

        float  o_carry = 0.0f;
        float* gprev   = &g_oscr[(blockIdx.x & 127) * 8 + rloc];

        for (int c = 0; c < NCH; ++c) {
            __syncthreads();   // chunk c ready
            const float* cb = &buf[c & 1][0];
            float* gout = cell + ((size_t)b * TT + (size_t)c * SCH) * NST
                        + rb * 8 + rloc;
#pragma unroll 2
            for (int s = 0; s < SCH; ++s) {
                const float* p = cb + s * 256;

                float4 k4[4], q4[4];
                const float4* kp = (const float4*)(p + c0);
                const float4* qp = (const float4*)(p + 128 + c0);
#pragma unroll
                for (int i = 0; i < 4; i++) { k4[i] = kp[i]; q4[i] = qp[i]; }
                float axv = p[192 + r];
                float vv  = p[64 + r];

                // finish previous step's o while the LDS above are in flight
                {
                    float op = o_carry;
                    op += __shfl_xor_sync(0xffffffffu, op, 1);
                    op += __shfl_xor_sync(0xffffffffu, op, 2);
                    if (h == 0) {
                        float sg = fast_sigmoid(op);
                        *gprev = op * op * sg;   // o * silu(o)
                    }
                }

                float r0 = 0.f, r1 = 0.f, r2 = 0.f, r3 = 0.f;
#pragma unroll
                for (int i = 0; i < 4; i++) {
                    r0 = fmaf(S[4 * i + 0], k4[i].x, r0);
                    r1 = fmaf(S[4 * i + 1], k4[i].y, r1);
                    r2 = fmaf(S[4 * i + 2], k4[i].z, r2);
                    r3 = fmaf(S[4 * i + 3], k4[i].w, r3);
                }
                float rp = (r0 + r1) + (r2 + r3);
                rp += __shfl_xor_sync(0xffffffffu, rp, 1);
                rp += __shfl_xor_sync(0xffffffffu, rp, 2);

                float araw = fmaf(dA, rp, axv + bA);
                float al   = fast_sigmoid(araw);
                float cc   = (1.0f - al) * vv;

                float o0 = 0.f, o1 = 0.f, o2 = 0.f, o3 = 0.f;
#pragma unroll
                for (int i = 0; i < 4; i++) {
                    S[4 * i + 0] = fmaf(al, S[4 * i + 0], cc * k4[i].x);
                    S[4 * i + 1] = fmaf(al, S[4 * i + 1], cc * k4[i].y);
                    S[4 * i + 2] = fmaf(al, S[4 * i + 2], cc * k4[i].z);
                    S[4 * i + 3] = fmaf(al, S[4 * i + 3], cc * k4[i].w);
                    o0 = fmaf(S[4 * i + 0], q4[i].x, o0);
                    o1 = fmaf(S[4 * i + 1], q4[i].y, o1);
                    o2 = fmaf(S[4 * i + 2], q4[i].z, o2);
                    o3 = fmaf(S[4 * i + 3], q4[i].w, o3);
                }
                o_carry = (o0 + o1) + (o2 + o3);
                gprev   = gout + (size_t)s * NST;
            }
            __syncthreads();   // release buf[c&1] for refill
        }

        // flush last deferred o
        {
            float op = o_carry;
            op += __shfl_xor_sync(0xffffffffu, op, 1);
            op += __shfl_xor_sync(0xffffffffu, op, 2);
            if (h == 0) {
                float sg = fast_sigmoid(op);
                *gprev = op * op * sg;
            }
        }

        float* sp = S_out + (size_t)b * (NST * NST) + (size_t)r * NST + c0;
#pragma unroll
        for (int i = 0; i < 4; i++)
            ((float4*)sp)[i] = make_float4(S[4 * i + 0], S[4 * i + 1],
                                           S[4 * i + 2], S[4 * i + 3]);
    }
}

// ---------------------------------------------------------------------------
// Launch
// ---------------------------------------------------------------------------
extern "C" void kernel_launch(void* const* d_in, const int* in_sizes, int n_in,
                              void* d_out, int out_size) {
    const float* x   = (const float*)d_in[0];
    const float* Win = (const float*)d_in[1];
    const float* Wk  = (const float*)d_in[2];
    const float* Wv  = (const float*)d_in[3];
    const float* Wq  = (const float*)d_in[4];
    const float* Wa  = (const float*)d_in[5];
    const float* dAl = (const float*)d_in[6];
    const float* bAl = (const float*)d_in[7];
    const float* Wout= (const float*)d_in[8];
    float* out = (float*)d_out;

    void *xhh_v, *xhl_v, *xph_v, *xpl_v, *wih_v, *wch_v, *kvqa_v, *cell_v;
    cudaGetSymbolAddress(&xhh_v, g_xhh);  cudaGetSymbolAddress(&xhl_v, g_xhl);
    cudaGetSymbolAddress(&xph_v, g_xph);  cudaGetSymbolAddress(&xpl_v, g_xpl);
    cudaGetSymbolAddress(&wih_v, g_wih);  cudaGetSymbolAddress(&wch_v, g_wch);
    cudaGetSymbolAddress(&kvqa_v, g_kvqa);
    cudaGetSymbolAddress(&cell_v, g_cell);
    __half* xhh = (__half*)xhh_v;  __half* xhl = (__half*)xhl_v;
    __half* xph = (__half*)xph_v;  __half* xpl = (__half*)xpl_v;
    __half* wih = (__half*)wih_v;  __half* wch = (__half*)wch_v;
    float* kvqa = (float*)kvqa_v;
    float* cell = (float*)cell_v;

    cudaFuncSetAttribute(hgemm_kernel<0>,
                         cudaFuncAttributeMaxDynamicSharedMemorySize, SMEM_H);
    cudaFuncSetAttribute(hgemm_kernel<1>,
                         cudaFuncAttributeMaxDynamicSharedMemorySize, SMEM_H);

    // 0) conversions
    conv_hl_kernel<<<(MTOT * DIM / 8 + 255) / 256, 256>>>(x, xhh, xhl,
                                                          MTOT * DIM / 8);
    conv_h_kernel<<<(DIM * DIM / 8 + 255) / 256, 256>>>(Win, wih,
                                                        DIM * DIM / 8);
    conv_wcat_kernel<<<(256 * DIM / 8 + 255) / 256, 256>>>(Wk, Wv, Wq, Wa,
                                                           wch);

    // 1) xp = silu(x @ W_in^T)  (M=32768, N=1024, K=1024) -> fp16 hi/lo
    hgemm_kernel<1><<<dim3(DIM / BN, MTOT / BM), 256, SMEM_H>>>(
        xhh, xhl, wih, nullptr, xph, xpl, DIM, DIM);

    // 2) kvqa = xp @ Wcat^T  (M=32768, N=256, K=1024) -> fp32
    hgemm_kernel<0><<<dim3(256 / BN, MTOT / BM), 256, SMEM_H>>>(
        xph, xpl, wch, kvqa, nullptr, nullptr, 256, DIM);

    // 3) warp-specialized scan with deferred o (S_final to d_out tail)
    scan_kernel<<<BB * 8, 128>>>(kvqa, dAl, bAl, cell,
                                 out + (size_t)MTOT * DIM);

    // 4) output = cell @ W_out^T  (M=32768, N=1024, K=64)
    sgemm_kernel<<<dim3(DIM / 128, MTOT / 128), 256>>>(
        cell, Wout, out, MTOT, DIM, NST);
}